// round 3
// baseline (speedup 1.0000x reference)
#include <cuda_runtime.h>
#include <math.h>

#define BB   32
#define CC   4
#define DD   768
#define HH   12
#define LL   12
#define HID  3072
#define NP   256
#define TT   (BB*NP)    // 8192 tokens
#define BHH  (BB*HH)    // 384

// ---------------- scratch (static device allocations; no cudaMalloc) ----------
__device__ float g_tok [TT*DD];
__device__ float g_hmod[TT*DD];
__device__ float g_o   [TT*DD];
__device__ float g_qkv [TT*3*DD];
__device__ float g_attn[(size_t)BHH*NP*NP];
__device__ float g_hmid[(size_t)TT*HID];
__device__ float g_c0  [BB*DD];
__device__ float g_tmid[BB*HID];
__device__ float g_c   [BB*DD];
__device__ float g_sc  [BB*DD];
__device__ float g_ada [BB*6*DD];
__device__ float g_adaf[BB*2*DD];

// ---------------- f32x2 helpers ----------------
__device__ __forceinline__ unsigned long long pack2(float x){
    unsigned long long r;
    asm("mov.b64 %0, {%1, %1};" : "=l"(r) : "f"(x));
    return r;
}
__device__ __forceinline__ void fma2(unsigned long long &acc, unsigned long long a, unsigned long long b){
    asm("fma.rn.f32x2 %0, %1, %2, %0;" : "+l"(acc) : "l"(a), "l"(b));
}
__device__ __forceinline__ float2 unpack2(unsigned long long v){
    float2 r;
    asm("mov.b64 {%0, %1}, %2;" : "=f"(r.x), "=f"(r.y) : "l"(v));
    return r;
}
__device__ __forceinline__ float gelu_f(float x){
    return 0.5f * x * (1.0f + erff(x * 0.7071067811865475f));
}

// ---------------- main GEMM: C[M,N] = A[M,K] @ W[K,N], epilogues --------------
// EP 0: out = acc + bias          (qkv)
// EP 1: out = gelu(acc + bias)    (mlp1)
// EP 2: out += gate[b,n]*(acc+b)  (residual, gate stride 6*DD)
template<int EP>
__global__ void __launch_bounds__(256) gemm128(
    const float* __restrict__ A, const float* __restrict__ W,
    const float* __restrict__ bias, float* __restrict__ out,
    int M, int N, int K, const float* __restrict__ gate, int gateOff)
{
    __shared__ __align__(16) float sA[2][16][132];
    __shared__ __align__(16) float sB[2][16][128];
    const int tid = threadIdx.x;
    const int tx = tid & 15, ty = tid >> 4;
    const int n0 = blockIdx.x * 128;
    const int m0 = blockIdx.y * 128;

    unsigned long long acc[8][4];
#pragma unroll
    for (int i = 0; i < 8; i++)
#pragma unroll
        for (int j = 0; j < 4; j++) acc[i][j] = 0ull;

    const int arow0 = tid >> 2, ac4 = tid & 3;
    const int krow0 = tid >> 5, bc4 = tid & 31;

    // load tile 0
    {
#pragma unroll
        for (int li = 0; li < 2; ++li){
            int arow = arow0 + li*64;
            float4 v = *(const float4*)(A + (size_t)(m0+arow)*K + ac4*4);
            sA[0][ac4*4+0][arow]=v.x; sA[0][ac4*4+1][arow]=v.y;
            sA[0][ac4*4+2][arow]=v.z; sA[0][ac4*4+3][arow]=v.w;
        }
#pragma unroll
        for (int li = 0; li < 2; ++li){
            int krow = krow0 + li*8;
            float4 v = *(const float4*)(W + (size_t)krow*N + n0 + bc4*4);
            *(float4*)&sB[0][krow][bc4*4] = v;
        }
    }
    __syncthreads();

    const int nk = K >> 4;
    for (int t = 0; t < nk; ++t){
        const int cur = t & 1;
        float4 pa0, pa1, pb0, pb1;
        if (t + 1 < nk){
            const int kt = (t+1) << 4;
            pa0 = *(const float4*)(A + (size_t)(m0+arow0   )*K + kt + ac4*4);
            pa1 = *(const float4*)(A + (size_t)(m0+arow0+64)*K + kt + ac4*4);
            pb0 = *(const float4*)(W + (size_t)(kt+krow0  )*N + n0 + bc4*4);
            pb1 = *(const float4*)(W + (size_t)(kt+krow0+8)*N + n0 + bc4*4);
        }
#pragma unroll
        for (int k = 0; k < 16; ++k){
            float4 a0 = *(const float4*)&sA[cur][k][ty*8];
            float4 a1 = *(const float4*)&sA[cur][k][ty*8+4];
            const unsigned long long* pb = (const unsigned long long*)&sB[cur][k][tx*8];
            unsigned long long b0 = pb[0], b1 = pb[1], b2 = pb[2], b3 = pb[3];
            float av[8] = {a0.x,a0.y,a0.z,a0.w,a1.x,a1.y,a1.z,a1.w};
#pragma unroll
            for (int i = 0; i < 8; i++){
                unsigned long long aa = pack2(av[i]);
                fma2(acc[i][0], aa, b0);
                fma2(acc[i][1], aa, b1);
                fma2(acc[i][2], aa, b2);
                fma2(acc[i][3], aa, b3);
            }
        }
        if (t + 1 < nk){
            const int nxt = cur ^ 1;
            sA[nxt][ac4*4+0][arow0]=pa0.x; sA[nxt][ac4*4+1][arow0]=pa0.y;
            sA[nxt][ac4*4+2][arow0]=pa0.z; sA[nxt][ac4*4+3][arow0]=pa0.w;
            sA[nxt][ac4*4+0][arow0+64]=pa1.x; sA[nxt][ac4*4+1][arow0+64]=pa1.y;
            sA[nxt][ac4*4+2][arow0+64]=pa1.z; sA[nxt][ac4*4+3][arow0+64]=pa1.w;
            *(float4*)&sB[nxt][krow0  ][bc4*4] = pb0;
            *(float4*)&sB[nxt][krow0+8][bc4*4] = pb1;
        }
        __syncthreads();
    }

    const int nb = n0 + tx*8;
    const int mb = m0 + ty*8;
#pragma unroll
    for (int i = 0; i < 8; i++){
        const int m = mb + i;
        float* orow = out + (size_t)m*N + nb;
        const float* gr = (EP == 2) ? (gate + (size_t)(m >> 8)*(6*DD) + gateOff + nb) : nullptr;
#pragma unroll
        for (int j = 0; j < 4; j++){
            float2 c = unpack2(acc[i][j]);
            float v0 = c.x + bias[nb + 2*j];
            float v1 = c.y + bias[nb + 2*j + 1];
            if (EP == 0){ orow[2*j] = v0; orow[2*j+1] = v1; }
            else if (EP == 1){ orow[2*j] = gelu_f(v0); orow[2*j+1] = gelu_f(v1); }
            else { orow[2*j] += gr[2*j]*v0; orow[2*j+1] += gr[2*j+1]*v1; }
        }
    }
}

// ---------------- small-M (M=32) GEMM for conditioning ----------------
// EP 0: silu(acc+bias)   EP 1: acc+bias+cls_emb[label]   EP 2: acc+bias
template<int EP>
__global__ void __launch_bounds__(256) gemm_small(
    const float* __restrict__ A, const float* __restrict__ W,
    const float* __restrict__ bias, float* __restrict__ out,
    int N, int K, const float* __restrict__ cls, const int* __restrict__ lab)
{
    __shared__ float sA[32][64];
    const int tid = threadIdx.x;
    const int nl = tid & 63, rb = tid >> 6;
    const int n = blockIdx.x*64 + nl;
    float acc[8];
#pragma unroll
    for (int r = 0; r < 8; r++) acc[r] = 0.f;
    for (int kt = 0; kt < K; kt += 64){
        __syncthreads();
#pragma unroll
        for (int r = 0; r < 8; r++){
            int idx = tid + r*256;
            sA[idx>>6][idx&63] = A[(size_t)(idx>>6)*K + kt + (idx&63)];
        }
        __syncthreads();
#pragma unroll 8
        for (int k = 0; k < 64; k++){
            float w = W[(size_t)(kt+k)*N + n];
#pragma unroll
            for (int r = 0; r < 8; r++) acc[r] = fmaf(sA[rb + r*4][k], w, acc[r]);
        }
    }
    const float b = bias[n];
#pragma unroll
    for (int r = 0; r < 8; r++){
        const int row = rb + r*4;
        float v = acc[r] + b;
        if (EP == 0) v = v / (1.f + expf(-v));
        else if (EP == 1) v += cls[(size_t)lab[row]*DD + n];
        out[(size_t)row*N + n] = v;
    }
}

// ---------------- elementwise / embedding kernels ----------------
__global__ void silu_k(const float* __restrict__ in, float* __restrict__ out, int n){
    int i = blockIdx.x*256 + threadIdx.x;
    if (i < n){ float v = in[i]; out[i] = v / (1.f + expf(-v)); }
}

__global__ void time_embed_k(const float* __restrict__ t, float* __restrict__ c0){
    int b = blockIdx.x, j = threadIdx.x;  // 384 threads
    float e = t[b] * expf(-(float)j * (9.210340371976184f / 383.f));
    c0[b*DD + j]       = sinf(e);
    c0[b*DD + 384 + j] = cosf(e);
}

__global__ void patchify_k(const float* __restrict__ x, const float* __restrict__ cw,
                           const float* __restrict__ cb, float* __restrict__ tok){
    __shared__ float xv[16];
    const int t = blockIdx.x, tid = threadIdx.x;
    const int b = t>>8, n = t&255, gy = n>>4, gx = n&15;
    if (tid < 16){
        int c = tid>>2, p1 = (tid>>1)&1, p2 = tid&1;
        xv[tid] = x[((b*4+c)*32 + gy*2+p1)*32 + gx*2+p2];
    }
    __syncthreads();
    for (int d = tid; d < DD; d += 256){
        const float4* w4 = (const float4*)(cw + d*16);
        float s = cb[d];
#pragma unroll
        for (int q = 0; q < 4; q++){
            float4 w = w4[q];
            s += xv[q*4+0]*w.x + xv[q*4+1]*w.y + xv[q*4+2]*w.z + xv[q*4+3]*w.w;
        }
        int i2 = d & ~1;  // 2*(d/2)
        float ang = (float)n * expf(-(float)i2 * (9.210340371976184f / 768.f));
        float pe = (d & 1) ? cosf(ang) : sinf(ang);
        tok[(size_t)t*DD + d] = s + pe;
    }
}

__global__ void ln_mod_k(const float* __restrict__ in, const float* __restrict__ ada,
                         int adaStride, int shOff, int scOff, float* __restrict__ out){
    const int t = blockIdx.x, tid = threadIdx.x;
    const float* row = in + (size_t)t*DD;
    float x0 = row[tid], x1 = row[tid+256], x2 = row[tid+512];
    float sum = x0 + x1 + x2;
    float sq  = fmaf(x0,x0, fmaf(x1,x1, x2*x2));
    __shared__ float s1[8], s2[8];
#pragma unroll
    for (int o = 16; o; o >>= 1){
        sum += __shfl_xor_sync(0xffffffffu, sum, o);
        sq  += __shfl_xor_sync(0xffffffffu, sq,  o);
    }
    if ((tid & 31) == 0){ s1[tid>>5] = sum; s2[tid>>5] = sq; }
    __syncthreads();
    float tot = 0.f, totq = 0.f;
#pragma unroll
    for (int w = 0; w < 8; w++){ tot += s1[w]; totq += s2[w]; }
    float m   = tot * (1.f/768.f);
    float var = totq * (1.f/768.f) - m*m;
    float r   = rsqrtf(var + 1e-6f);
    const int b = t >> 8;
    const float* sh = ada + (size_t)b*adaStride + shOff;
    const float* sc = ada + (size_t)b*adaStride + scOff;
    float* orow = out + (size_t)t*DD;
    orow[tid]     = (x0-m)*r*(1.f+sc[tid])     + sh[tid];
    orow[tid+256] = (x1-m)*r*(1.f+sc[tid+256]) + sh[tid+256];
    orow[tid+512] = (x2-m)*r*(1.f+sc[tid+512]) + sh[tid+512];
}

// ---------------- attention ----------------
__global__ void __launch_bounds__(256) scores_k(const float* __restrict__ qkv, float* __restrict__ attn){
    __shared__ __align__(16) float sQ[16][68];
    __shared__ __align__(16) float sK[16][68];
    const int bh = blockIdx.z, b = bh/12, h = bh%12;
    const int n0 = blockIdx.y*64, m0 = blockIdx.x*64;
    const int tid = threadIdx.x, tx = tid&15, ty = tid>>4;
    float acc[4][4] = {};
    const int lr = tid>>2, lc4 = tid&3;
    const float* qbase = qkv + (size_t)b*NP*2304 + h*64;
    for (int dk = 0; dk < 64; dk += 16){
        __syncthreads();
        {
            float4 v = *(const float4*)(qbase + (size_t)(n0+lr)*2304 + dk + lc4*4);
            sQ[lc4*4+0][lr]=v.x; sQ[lc4*4+1][lr]=v.y; sQ[lc4*4+2][lr]=v.z; sQ[lc4*4+3][lr]=v.w;
            float4 u = *(const float4*)(qbase + 768 + (size_t)(m0+lr)*2304 + dk + lc4*4);
            sK[lc4*4+0][lr]=u.x; sK[lc4*4+1][lr]=u.y; sK[lc4*4+2][lr]=u.z; sK[lc4*4+3][lr]=u.w;
        }
        __syncthreads();
#pragma unroll
        for (int k = 0; k < 16; k++){
            float4 a = *(const float4*)&sQ[k][ty*4];
            float4 c = *(const float4*)&sK[k][tx*4];
            float av[4]={a.x,a.y,a.z,a.w}, bv[4]={c.x,c.y,c.z,c.w};
#pragma unroll
            for (int i = 0; i < 4; i++)
#pragma unroll
                for (int j = 0; j < 4; j++) acc[i][j] = fmaf(av[i], bv[j], acc[i][j]);
        }
    }
#pragma unroll
    for (int i = 0; i < 4; i++){
        float4 v = make_float4(acc[i][0]*0.125f, acc[i][1]*0.125f, acc[i][2]*0.125f, acc[i][3]*0.125f);
        *(float4*)(attn + ((size_t)bh*NP + n0+ty*4+i)*NP + m0 + tx*4) = v;
    }
}

__global__ void softmax_k(float* __restrict__ attn){
    const int warp = threadIdx.x>>5, lane = threadIdx.x&31;
    const size_t row = (size_t)blockIdx.x*8 + warp;
    float* p = attn + row*NP;
    float v[8];
#pragma unroll
    for (int j = 0; j < 8; j++) v[j] = p[lane + j*32];
    float mx = v[0];
#pragma unroll
    for (int j = 1; j < 8; j++) mx = fmaxf(mx, v[j]);
#pragma unroll
    for (int o = 16; o; o >>= 1) mx = fmaxf(mx, __shfl_xor_sync(0xffffffffu, mx, o));
    float s = 0.f;
#pragma unroll
    for (int j = 0; j < 8; j++){ v[j] = expf(v[j]-mx); s += v[j]; }
#pragma unroll
    for (int o = 16; o; o >>= 1) s += __shfl_xor_sync(0xffffffffu, s, o);
    const float inv = 1.f/s;
#pragma unroll
    for (int j = 0; j < 8; j++) p[lane + j*32] = v[j]*inv;
}

__global__ void __launch_bounds__(256) attnv_k(const float* __restrict__ attn,
                                               const float* __restrict__ qkv,
                                               float* __restrict__ o){
    __shared__ __align__(16) float sP[16][68];
    __shared__ __align__(16) float sV[16][64];
    const int bh = blockIdx.x, b = bh/12, h = bh%12;
    const int ny0 = blockIdx.y*64;
    const int tid = threadIdx.x, tx = tid&15, ty = tid>>4;
    float acc[4][4] = {};
    const int lr = tid>>2, lc4 = tid&3;
    const int vr = tid>>4, vc4 = tid&15;
    const float* vbase = qkv + (size_t)b*NP*2304 + 1536 + h*64;
    const float* prow  = attn + ((size_t)bh*NP + ny0)*NP;
    for (int m0 = 0; m0 < NP; m0 += 16){
        __syncthreads();
        {
            float4 v = *(const float4*)(prow + (size_t)lr*NP + m0 + lc4*4);
            sP[lc4*4+0][lr]=v.x; sP[lc4*4+1][lr]=v.y; sP[lc4*4+2][lr]=v.z; sP[lc4*4+3][lr]=v.w;
            float4 u = *(const float4*)(vbase + (size_t)(m0+vr)*2304 + vc4*4);
            *(float4*)&sV[vr][vc4*4] = u;
        }
        __syncthreads();
#pragma unroll
        for (int m = 0; m < 16; m++){
            float4 a = *(const float4*)&sP[m][ty*4];
            float4 c = *(const float4*)&sV[m][tx*4];
            float av[4]={a.x,a.y,a.z,a.w}, bv[4]={c.x,c.y,c.z,c.w};
#pragma unroll
            for (int i = 0; i < 4; i++)
#pragma unroll
                for (int j = 0; j < 4; j++) acc[i][j] = fmaf(av[i], bv[j], acc[i][j]);
        }
    }
#pragma unroll
    for (int i = 0; i < 4; i++){
        *(float4*)(o + (size_t)(b*NP + ny0 + ty*4 + i)*DD + h*64 + tx*4) =
            make_float4(acc[i][0], acc[i][1], acc[i][2], acc[i][3]);
    }
}

// ---------------- final head + unpatchify ----------------
__global__ void final_k(const float* __restrict__ hmod, const float* __restrict__ w,
                        const float* __restrict__ bias, float* __restrict__ out){
    __shared__ float row[768];
    __shared__ float red[128];
    const int t = blockIdx.x, tid = threadIdx.x;  // 128 threads
#pragma unroll
    for (int r = 0; r < 6; r++) row[tid + r*128] = hmod[(size_t)t*DD + tid + r*128];
    __syncthreads();
    const int j = tid & 15, p = tid >> 4;
    float s = 0.f;
#pragma unroll 8
    for (int k = p*96; k < p*96 + 96; ++k) s = fmaf(row[k], w[k*16 + j], s);
    red[tid] = s;
    __syncthreads();
    if (tid < 16){
        float tot = bias[tid];
#pragma unroll
        for (int q = 0; q < 8; q++) tot += red[q*16 + tid];
        const int b = t>>8, n = t&255, gy = n>>4, gx = n&15;
        const int c = tid&3, pq = tid>>2, p1 = pq>>1, p2 = pq&1;
        out[((b*4+c)*32 + gy*2+p1)*32 + gx*2+p2] = tot;
    }
}

// ---------------- host launcher ----------------
extern "C" void kernel_launch(void* const* d_in, const int* in_sizes, int n_in,
                              void* d_out, int out_size){
    (void)in_sizes; (void)n_in; (void)out_size;
    const float* x     = (const float*)d_in[0];
    const float* tt    = (const float*)d_in[1];
    const float* convw = (const float*)d_in[2];
    const float* convb = (const float*)d_in[3];
    const float* tw1   = (const float*)d_in[4];
    const float* tb1   = (const float*)d_in[5];
    const float* tw2   = (const float*)d_in[6];
    const float* tb2   = (const float*)d_in[7];
    const float* cls   = (const float*)d_in[8];
    const float* qkvw  = (const float*)d_in[9];
    const float* qkvb  = (const float*)d_in[10];
    const float* ow    = (const float*)d_in[11];
    const float* ob    = (const float*)d_in[12];
    const float* aw    = (const float*)d_in[13];
    const float* ab    = (const float*)d_in[14];
    const float* m1w   = (const float*)d_in[15];
    const float* m1b   = (const float*)d_in[16];
    const float* m2w   = (const float*)d_in[17];
    const float* m2b   = (const float*)d_in[18];
    const float* faw   = (const float*)d_in[19];
    const float* fab   = (const float*)d_in[20];
    const float* flw   = (const float*)d_in[21];
    const float* flb   = (const float*)d_in[22];
    const int*   lab   = (const int*)d_in[23];
    float* out = (float*)d_out;

    float *tok,*hmod,*o,*qkv,*attn,*hmid,*c0,*tmid,*c,*sc,*ada,*adaf;
    cudaGetSymbolAddress((void**)&tok,  g_tok);
    cudaGetSymbolAddress((void**)&hmod, g_hmod);
    cudaGetSymbolAddress((void**)&o,    g_o);
    cudaGetSymbolAddress((void**)&qkv,  g_qkv);
    cudaGetSymbolAddress((void**)&attn, g_attn);
    cudaGetSymbolAddress((void**)&hmid, g_hmid);
    cudaGetSymbolAddress((void**)&c0,   g_c0);
    cudaGetSymbolAddress((void**)&tmid, g_tmid);
    cudaGetSymbolAddress((void**)&c,    g_c);
    cudaGetSymbolAddress((void**)&sc,   g_sc);
    cudaGetSymbolAddress((void**)&ada,  g_ada);
    cudaGetSymbolAddress((void**)&adaf, g_adaf);

    patchify_k<<<TT, 256>>>(x, convw, convb, tok);
    time_embed_k<<<BB, 384>>>(tt, c0);
    gemm_small<0><<<HID/64, 256>>>(c0,   tw1, tb1, tmid, HID, DD,  nullptr, nullptr);
    gemm_small<1><<<DD/64,  256>>>(tmid, tw2, tb2, c,    DD,  HID, cls, lab);
    silu_k<<<(BB*DD + 255)/256, 256>>>(c, sc, BB*DD);

    for (int i = 0; i < LL; i++){
        gemm_small<2><<<(6*DD)/64, 256>>>(sc, aw + (size_t)i*DD*6*DD, ab + (size_t)i*6*DD,
                                          ada, 6*DD, DD, nullptr, nullptr);
        // attention branch
        ln_mod_k<<<TT, 256>>>(tok, ada, 6*DD, 0, DD, hmod);
        gemm128<0><<<dim3((3*DD)/128, TT/128), 256>>>(hmod, qkvw + (size_t)i*DD*3*DD,
                                                      qkvb + (size_t)i*3*DD, qkv,
                                                      TT, 3*DD, DD, nullptr, 0);
        scores_k<<<dim3(4,4,BHH), 256>>>(qkv, attn);
        softmax_k<<<(BHH*NP)/8, 256>>>(attn);
        attnv_k<<<dim3(BHH,4), 256>>>(attn, qkv, o);
        gemm128<2><<<dim3(DD/128, TT/128), 256>>>(o, ow + (size_t)i*DD*DD,
                                                  ob + (size_t)i*DD, tok,
                                                  TT, DD, DD, ada, 2*DD);
        // mlp branch
        ln_mod_k<<<TT, 256>>>(tok, ada, 6*DD, 3*DD, 4*DD, hmod);
        gemm128<1><<<dim3(HID/128, TT/128), 256>>>(hmod, m1w + (size_t)i*DD*HID,
                                                   m1b + (size_t)i*HID, hmid,
                                                   TT, HID, DD, nullptr, 0);
        gemm128<2><<<dim3(DD/128, TT/128), 256>>>(hmid, m2w + (size_t)i*HID*DD,
                                                  m2b + (size_t)i*DD, tok,
                                                  TT, DD, HID, ada, 5*DD);
    }

    gemm_small<2><<<(2*DD)/64, 256>>>(sc, faw, fab, adaf, 2*DD, DD, nullptr, nullptr);
    ln_mod_k<<<TT, 256>>>(tok, adaf, 2*DD, 0, DD, hmod);
    final_k<<<TT, 128>>>(hmod, flw, flb, out);
}

// round 5
// speedup vs baseline: 1.7769x; 1.7769x over previous
#include <cuda_runtime.h>
#include <cuda_bf16.h>
#include <math.h>
#include <stdint.h>

#define BB   32
#define CC   4
#define DD   768
#define HH   12
#define LL   12
#define HID  3072
#define NP   256
#define TT   (BB*NP)    // 8192 tokens
#define BHH  (BB*HH)    // 384

// ---------------- scratch (static device allocations; no cudaMalloc) ----------
__device__ float g_tok [TT*DD];
__device__ float g_hmod[TT*DD];
__device__ float g_o   [TT*DD];
__device__ float g_qkv [TT*3*DD];
__device__ float g_attn[(size_t)BHH*NP*NP];
__device__ float g_hmid[(size_t)TT*HID];
__device__ float g_c0  [128*DD];        // padded to 128 rows (rows 32+ stay 0)
__device__ float g_tmid[128*HID];       // padded
__device__ float g_c   [BB*DD];
__device__ float g_sc  [128*DD];        // padded
__device__ float g_ada [LL*BB*6*DD];
__device__ float g_adaf[BB*2*DD];
// transposed weights [N,K]
__device__ float g_qkvwT[(size_t)LL*3*DD*DD];
__device__ float g_owT  [(size_t)LL*DD*DD];
__device__ float g_m1wT [(size_t)LL*HID*DD];
__device__ float g_m2wT [(size_t)LL*DD*HID];
__device__ float g_awT  [(size_t)LL*6*DD*DD];
__device__ float g_tw1T [(size_t)HID*DD];
__device__ float g_tw2T [(size_t)DD*HID];
__device__ float g_fawT [(size_t)2*DD*DD];

// ---------------- helpers ----------------
__device__ __forceinline__ uint32_t sm32(const void* p){
    uint32_t a;
    asm("{ .reg .u64 t; cvta.to.shared.u64 t, %1; cvt.u32.u64 %0, t; }" : "=r"(a) : "l"(p));
    return a;
}
__device__ __forceinline__ void cvt_pair(float x0, float x1, uint32_t &hi, uint32_t &lo){
    __nv_bfloat16 h0 = __float2bfloat16(x0);
    __nv_bfloat16 h1 = __float2bfloat16(x1);
    float r0 = x0 - __bfloat162float(h0);
    float r1 = x1 - __bfloat162float(h1);
    __nv_bfloat16 l0 = __float2bfloat16(r0);
    __nv_bfloat16 l1 = __float2bfloat16(r1);
    hi = (uint32_t)__bfloat16_as_ushort(h0) | ((uint32_t)__bfloat16_as_ushort(h1) << 16);
    lo = (uint32_t)__bfloat16_as_ushort(l0) | ((uint32_t)__bfloat16_as_ushort(l1) << 16);
}
__device__ __forceinline__ void cvt4(float4 v, uint2 &hi, uint2 &lo){
    cvt_pair(v.x, v.y, hi.x, lo.x);
    cvt_pair(v.z, v.w, hi.y, lo.y);
}
__device__ __forceinline__ void ldsm4(uint32_t* r, uint32_t addr){
    asm volatile("ldmatrix.sync.aligned.m8n8.x4.shared.b16 {%0,%1,%2,%3}, [%4];"
        : "=r"(r[0]), "=r"(r[1]), "=r"(r[2]), "=r"(r[3]) : "r"(addr));
}
__device__ __forceinline__ void mma16816(float* d, uint32_t a0, uint32_t a1, uint32_t a2,
                                         uint32_t a3, uint32_t b0, uint32_t b1){
    asm volatile("mma.sync.aligned.m16n8k16.row.col.f32.bf16.bf16.f32 "
        "{%0,%1,%2,%3}, {%4,%5,%6,%7}, {%8,%9}, {%0,%1,%2,%3};"
        : "+f"(d[0]), "+f"(d[1]), "+f"(d[2]), "+f"(d[3])
        : "r"(a0), "r"(a1), "r"(a2), "r"(a3), "r"(b0), "r"(b1));
}
__device__ __forceinline__ float gelu_f(float x){
    return 0.5f * x * (1.0f + erff(x * 0.7071067811865475f));
}
__device__ __forceinline__ float silu_f(float x){
    return x / (1.f + expf(-x));
}

// ---- bf16x3 K=32 chunk micro-kernel. smem tiles are bf16, row stride RS bytes.
// A: [rows][k] hi at oAh, lo at oAl; B(=W^T): [n][k] hi at oBh, lo at oBl.
// d is [MI][NPAIRS*2] accum blocks of 4 floats, flattened: d[mi*(NPAIRS*2)+ni].
template<int MI, int NPAIRS, int RS>
__device__ __forceinline__ void mma_chunk(uint32_t sb, int oAh, int oAl, int oBh, int oBl,
                                          int mrow0, int ncol0, int lane, float (*d)[4]){
    const int r8 = lane & 7, t1 = (lane >> 3) & 1, t2 = (lane >> 4) & 1;
#pragma unroll
    for (int ks = 0; ks < 2; ++ks){
        uint32_t ah[MI][4], al[MI][4];
        const int keA = ks*16 + t2*8;
        const int keB = ks*16 + t1*8;
#pragma unroll
        for (int mi = 0; mi < MI; ++mi){
            const int row = mrow0 + mi*16 + r8 + t1*8;
            ldsm4(ah[mi], sb + oAh + row*RS + keA*2);
            ldsm4(al[mi], sb + oAl + row*RS + keA*2);
        }
#pragma unroll
        for (int p = 0; p < NPAIRS; ++p){
            const int n = ncol0 + p*16 + r8 + t2*8;
            uint32_t bh[4], bl[4];
            ldsm4(bh, sb + oBh + n*RS + keB*2);
            ldsm4(bl, sb + oBl + n*RS + keB*2);
#pragma unroll
            for (int mi = 0; mi < MI; ++mi){
                float* d0 = d[mi*(NPAIRS*2) + p*2];
                float* d1 = d[mi*(NPAIRS*2) + p*2 + 1];
                mma16816(d0, ah[mi][0], ah[mi][1], ah[mi][2], ah[mi][3], bh[0], bh[1]);
                mma16816(d0, ah[mi][0], ah[mi][1], ah[mi][2], ah[mi][3], bl[0], bl[1]);
                mma16816(d0, al[mi][0], al[mi][1], al[mi][2], al[mi][3], bh[0], bh[1]);
                mma16816(d1, ah[mi][0], ah[mi][1], ah[mi][2], ah[mi][3], bh[2], bh[3]);
                mma16816(d1, ah[mi][0], ah[mi][1], ah[mi][2], ah[mi][3], bl[2], bl[3]);
                mma16816(d1, al[mi][0], al[mi][1], al[mi][2], al[mi][3], bh[2], bh[3]);
            }
        }
    }
}

// ---------------- main tensor GEMM: out[M,N] = A[M,K] @ Wt[N,K]^T ----------
// EP 0: acc+bias   1: gelu   2: out += gate*(acc+bias)   3: silu   4: +cls[lab[m]]
// smem per stage (40960B): Ah@0, Al@10240, Bh@20480, Bl@30720; rows 128 x 40 bf16 (80B)
#define GTC_SMEM 81920
template<int EP>
__global__ void __launch_bounds__(256) gemm_tc(
    const float* __restrict__ A, const float* __restrict__ Wt,
    const float* __restrict__ bias, float* __restrict__ out,
    int Mvalid, int N, int K,
    const float* __restrict__ aux, int auxOff, const int* __restrict__ lab,
    long long wz, long long bz, long long oz)
{
    extern __shared__ char smem[];
    const uint32_t sb = sm32(smem);
    const int tid = threadIdx.x, lane = tid & 31, wid = tid >> 5;
    const int warpM = wid & 1, warpN = wid >> 1;
    const int m0 = blockIdx.y*128, n0 = blockIdx.x*128, z = blockIdx.z;
    const float* Wz = Wt + (size_t)z*wz;
    const float* Bz = bias + (size_t)z*bz;
    float* Oz = out + (size_t)z*oz;

    float d[4][4][4];
#pragma unroll
    for (int i = 0; i < 4; ++i)
#pragma unroll
        for (int j = 0; j < 4; ++j)
#pragma unroll
            for (int k = 0; k < 4; ++k) d[i][j][k] = 0.f;

    const int lrow = tid >> 1, lq = tid & 1;
    const float* aR = A  + (size_t)(m0 + lrow)*K + lq*16;
    const float* bR = Wz + (size_t)(n0 + lrow)*K + lq*16;
    const int sOff = lrow*80 + lq*32;

    {
#pragma unroll
        for (int j = 0; j < 4; ++j){
            uint2 hi, lo;
            cvt4(*(const float4*)(aR + j*4), hi, lo);
            *(uint2*)(smem + sOff + j*8) = hi;
            *(uint2*)(smem + 10240 + sOff + j*8) = lo;
            cvt4(*(const float4*)(bR + j*4), hi, lo);
            *(uint2*)(smem + 20480 + sOff + j*8) = hi;
            *(uint2*)(smem + 30720 + sOff + j*8) = lo;
        }
    }
    __syncthreads();

    const int nk = K >> 5;
    for (int t = 0; t < nk; ++t){
        float4 va[4], vb[4];
        const bool pf = (t + 1 < nk);
        if (pf){
            const int kt = (t+1) << 5;
#pragma unroll
            for (int j = 0; j < 4; ++j){
                va[j] = *(const float4*)(aR + kt + j*4);
                vb[j] = *(const float4*)(bR + kt + j*4);
            }
        }
        mma_chunk<4,2,80>(sb + (uint32_t)(t&1)*40960u, 0, 10240, 20480, 30720,
                          warpM*64, warpN*32, lane, &d[0][0]);
        if (pf){
            char* sp = smem + ((t+1)&1)*40960;
#pragma unroll
            for (int j = 0; j < 4; ++j){
                uint2 hi, lo;
                cvt4(va[j], hi, lo);
                *(uint2*)(sp + sOff + j*8) = hi;
                *(uint2*)(sp + 10240 + sOff + j*8) = lo;
                cvt4(vb[j], hi, lo);
                *(uint2*)(sp + 20480 + sOff + j*8) = hi;
                *(uint2*)(sp + 30720 + sOff + j*8) = lo;
            }
        }
        __syncthreads();
    }

    const int g = lane >> 2, tig = lane & 3;
#pragma unroll
    for (int mi = 0; mi < 4; ++mi){
#pragma unroll
        for (int ni = 0; ni < 4; ++ni){
            const int n = n0 + warpN*32 + ni*8 + tig*2;
            const float2 bv = *(const float2*)(Bz + n);
            const int mA = m0 + warpM*64 + mi*16 + g;
#pragma unroll
            for (int hr = 0; hr < 2; ++hr){
                const int m = mA + hr*8;
                if (m < Mvalid){
                    float x0 = d[mi][ni][hr*2+0] + bv.x;
                    float x1 = d[mi][ni][hr*2+1] + bv.y;
                    float* op = Oz + (size_t)m*N + n;
                    if (EP == 0)      *(float2*)op = make_float2(x0, x1);
                    else if (EP == 1) *(float2*)op = make_float2(gelu_f(x0), gelu_f(x1));
                    else if (EP == 3) *(float2*)op = make_float2(silu_f(x0), silu_f(x1));
                    else if (EP == 4){
                        const float2 cv = *(const float2*)(aux + (size_t)lab[m]*DD + n);
                        *(float2*)op = make_float2(x0 + cv.x, x1 + cv.y);
                    } else {
                        const float2 gv = *(const float2*)(aux + (size_t)(m>>8)*(6*DD) + auxOff + n);
                        float2 ov = *(float2*)op;
                        *(float2*)op = make_float2(ov.x + gv.x*x0, ov.y + gv.y*x1);
                    }
                }
            }
        }
    }
}

// ---------------- attention scores: S = Q @ K^T * 0.125 (bf16x3) ----------
// smem (73728B): Qh@0, Ql@18432, Kh@36864, Kl@55296; rows 128 x 72 bf16 (144B)
#define SC_SMEM 73728
__global__ void __launch_bounds__(256) scores_tc(const float* __restrict__ qkv,
                                                 float* __restrict__ attn){
    extern __shared__ char smem[];
    const uint32_t sb = sm32(smem);
    const int tid = threadIdx.x, lane = tid & 31, wid = tid >> 5;
    const int warpM = wid & 1, warpN = wid >> 1;
    const int z = blockIdx.z, b = z/12, h = z%12;
    const int m0 = blockIdx.y*128, n0 = blockIdx.x*128;
    const float* qb = qkv + (size_t)b*NP*2304 + h*64;
    const float* kb = qb + 768;

    float d[4][4][4];
#pragma unroll
    for (int i = 0; i < 4; ++i)
#pragma unroll
        for (int j = 0; j < 4; ++j)
#pragma unroll
            for (int k = 0; k < 4; ++k) d[i][j][k] = 0.f;

    const int lrow = tid >> 1, lq = tid & 1;
    const int sOff = lrow*144 + lq*64;
    const float* qR = qb + (size_t)(m0 + lrow)*2304 + lq*32;
    const float* kR = kb + (size_t)(n0 + lrow)*2304 + lq*32;
#pragma unroll
    for (int j = 0; j < 8; ++j){
        uint2 hi, lo;
        cvt4(*(const float4*)(qR + j*4), hi, lo);
        *(uint2*)(smem + sOff + j*8) = hi;
        *(uint2*)(smem + 18432 + sOff + j*8) = lo;
        cvt4(*(const float4*)(kR + j*4), hi, lo);
        *(uint2*)(smem + 36864 + sOff + j*8) = hi;
        *(uint2*)(smem + 55296 + sOff + j*8) = lo;
    }
    __syncthreads();
    mma_chunk<4,2,144>(sb, 0,    18432,    36864,    55296,    warpM*64, warpN*32, lane, &d[0][0]);
    mma_chunk<4,2,144>(sb, 64,   18432+64, 36864+64, 55296+64, warpM*64, warpN*32, lane, &d[0][0]);

    const int g = lane >> 2, tig = lane & 3;
    float* ap = attn + (size_t)z*NP*NP;
#pragma unroll
    for (int mi = 0; mi < 4; ++mi)
#pragma unroll
        for (int ni = 0; ni < 4; ++ni){
            const int n = n0 + warpN*32 + ni*8 + tig*2;
            const int m = m0 + warpM*64 + mi*16 + g;
            *(float2*)(ap + (size_t)m*NP + n) =
                make_float2(d[mi][ni][0]*0.125f, d[mi][ni][1]*0.125f);
            *(float2*)(ap + (size_t)(m+8)*NP + n) =
                make_float2(d[mi][ni][2]*0.125f, d[mi][ni][3]*0.125f);
        }
}

// ---------------- attention AV: O = P @ V (bf16x3) ----------
// smem per stage (30720B): Ph@0, Pl@10240, Vh@20480, Vl@25600
// P rows 128 x 40 bf16 (80B); V^T rows 64 x 40 bf16 (80B)
#define AV_SMEM 61440
__global__ void __launch_bounds__(256) attnv_tc(const float* __restrict__ attn,
                                                const float* __restrict__ qkv,
                                                float* __restrict__ o){
    extern __shared__ char smem[];
    const uint32_t sb = sm32(smem);
    const int tid = threadIdx.x, lane = tid & 31, wid = tid >> 5;
    const int warpM = wid & 3, warpN = wid >> 2;
    const int z = blockIdx.y, b = z/12, h = z%12;
    const int m0 = blockIdx.x*128;
    const float* P  = attn + (size_t)z*NP*NP;
    const float* vb = qkv + (size_t)b*NP*2304 + 1536 + h*64;

    float d[2][4][4];
#pragma unroll
    for (int i = 0; i < 2; ++i)
#pragma unroll
        for (int j = 0; j < 4; ++j)
#pragma unroll
            for (int k = 0; k < 4; ++k) d[i][j][k] = 0.f;

    const int lrow = tid >> 1, lq = tid & 1;
    const int sOffA = lrow*80 + lq*32;
    const float* aR = P + (size_t)(m0 + lrow)*NP + lq*16;
    const int vk = tid >> 3, vn8 = tid & 7;

    auto storeA = [&](char* base, const float4* va){
#pragma unroll
        for (int j = 0; j < 4; ++j){
            uint2 hi, lo;
            cvt4(va[j], hi, lo);
            *(uint2*)(base + sOffA + j*8) = hi;
            *(uint2*)(base + 10240 + sOffA + j*8) = lo;
        }
    };
    auto storeB = [&](char* base, const float4* vv){
#pragma unroll
        for (int jj = 0; jj < 2; ++jj){
            const int n = vn8*8 + jj*4;
            const float xs[4] = {vv[jj].x, vv[jj].y, vv[jj].z, vv[jj].w};
#pragma unroll
            for (int e = 0; e < 4; ++e){
                __nv_bfloat16 hh = __float2bfloat16(xs[e]);
                __nv_bfloat16 ll = __float2bfloat16(xs[e] - __bfloat162float(hh));
                *(__nv_bfloat16*)(base + 20480 + (n+e)*80 + vk*2) = hh;
                *(__nv_bfloat16*)(base + 25600 + (n+e)*80 + vk*2) = ll;
            }
        }
    };

    {   // stage 0
        float4 va[4], vv[2];
#pragma unroll
        for (int j = 0; j < 4; ++j) va[j] = *(const float4*)(aR + j*4);
#pragma unroll
        for (int jj = 0; jj < 2; ++jj)
            vv[jj] = *(const float4*)(vb + (size_t)vk*2304 + vn8*8 + jj*4);
        storeA(smem, va); storeB(smem, vv);
    }
    __syncthreads();

    const int nk = NP >> 5;  // 8
    for (int t = 0; t < nk; ++t){
        float4 va[4], vv[2];
        const bool pf = (t + 1 < nk);
        if (pf){
            const int kt = (t+1) << 5;
#pragma unroll
            for (int j = 0; j < 4; ++j) va[j] = *(const float4*)(aR + kt + j*4);
#pragma unroll
            for (int jj = 0; jj < 2; ++jj)
                vv[jj] = *(const float4*)(vb + (size_t)(kt+vk)*2304 + vn8*8 + jj*4);
        }
        mma_chunk<2,2,80>(sb + (uint32_t)(t&1)*30720u, 0, 10240, 20480, 25600,
                          warpM*32, warpN*32, lane, &d[0][0]);
        if (pf){
            char* sp = smem + ((t+1)&1)*30720;
            storeA(sp, va); storeB(sp, vv);
        }
        __syncthreads();
    }

    const int g = lane >> 2, tig = lane & 3;
#pragma unroll
    for (int mi = 0; mi < 2; ++mi)
#pragma unroll
        for (int ni = 0; ni < 4; ++ni){
            const int m = m0 + warpM*32 + mi*16 + g;
            const int dc = warpN*32 + ni*8 + tig*2;
            float* op = o + (size_t)(b*NP + m)*DD + h*64 + dc;
            *(float2*)op = make_float2(d[mi][ni][0], d[mi][ni][1]);
            *(float2*)(o + (size_t)(b*NP + m + 8)*DD + h*64 + dc) =
                make_float2(d[mi][ni][2], d[mi][ni][3]);
        }
}

// ---------------- weight transpose: in[K,N] (z-batched) -> out[N,K] ----------
__global__ void transpose_k(const float* __restrict__ in, float* __restrict__ out,
                            int K, int N){
    __shared__ float tile[32][33];
    const size_t zoff = (size_t)blockIdx.z * K * N;
    const float* inz = in + zoff; float* outz = out + zoff;
    const int n0 = blockIdx.x*32, k0 = blockIdx.y*32;
    const int lx = threadIdx.x & 31, ly = threadIdx.x >> 5;
#pragma unroll
    for (int rr = 0; rr < 32; rr += 8)
        tile[ly+rr][lx] = inz[(size_t)(k0+ly+rr)*N + n0+lx];
    __syncthreads();
#pragma unroll
    for (int rr = 0; rr < 32; rr += 8)
        outz[(size_t)(n0+ly+rr)*K + k0+lx] = tile[lx][ly+rr];
}

// ---------------- elementwise / embedding kernels ----------------
__global__ void silu_k(const float* __restrict__ in, float* __restrict__ out, int n){
    int i = blockIdx.x*256 + threadIdx.x;
    if (i < n){ float v = in[i]; out[i] = v / (1.f + expf(-v)); }
}

__global__ void time_embed_k(const float* __restrict__ t, float* __restrict__ c0){
    int b = blockIdx.x, j = threadIdx.x;  // 384 threads
    float e = t[b] * expf(-(float)j * (9.210340371976184f / 383.f));
    c0[b*DD + j]       = sinf(e);
    c0[b*DD + 384 + j] = cosf(e);
}

__global__ void patchify_k(const float* __restrict__ x, const float* __restrict__ cw,
                           const float* __restrict__ cb, float* __restrict__ tok){
    __shared__ float xv[16];
    const int t = blockIdx.x, tid = threadIdx.x;
    const int b = t>>8, n = t&255, gy = n>>4, gx = n&15;
    if (tid < 16){
        int c = tid>>2, p1 = (tid>>1)&1, p2 = tid&1;
        xv[tid] = x[((b*4+c)*32 + gy*2+p1)*32 + gx*2+p2];
    }
    __syncthreads();
    for (int d = tid; d < DD; d += 256){
        const float4* w4 = (const float4*)(cw + d*16);
        float s = cb[d];
#pragma unroll
        for (int q = 0; q < 4; q++){
            float4 w = w4[q];
            s += xv[q*4+0]*w.x + xv[q*4+1]*w.y + xv[q*4+2]*w.z + xv[q*4+3]*w.w;
        }
        int i2 = d & ~1;
        float ang = (float)n * expf(-(float)i2 * (9.210340371976184f / 768.f));
        float pe = (d & 1) ? cosf(ang) : sinf(ang);
        tok[(size_t)t*DD + d] = s + pe;
    }
}

__global__ void ln_mod_k(const float* __restrict__ in, const float* __restrict__ ada,
                         int adaStride, int shOff, int scOff, float* __restrict__ out){
    const int t = blockIdx.x, tid = threadIdx.x;
    const float* row = in + (size_t)t*DD;
    float x0 = row[tid], x1 = row[tid+256], x2 = row[tid+512];
    float sum = x0 + x1 + x2;
    float sq  = fmaf(x0,x0, fmaf(x1,x1, x2*x2));
    __shared__ float s1[8], s2[8];
#pragma unroll
    for (int o = 16; o; o >>= 1){
        sum += __shfl_xor_sync(0xffffffffu, sum, o);
        sq  += __shfl_xor_sync(0xffffffffu, sq,  o);
    }
    if ((tid & 31) == 0){ s1[tid>>5] = sum; s2[tid>>5] = sq; }
    __syncthreads();
    float tot = 0.f, totq = 0.f;
#pragma unroll
    for (int w = 0; w < 8; w++){ tot += s1[w]; totq += s2[w]; }
    float m   = tot * (1.f/768.f);
    float var = totq * (1.f/768.f) - m*m;
    float rr  = rsqrtf(var + 1e-6f);
    const int b = t >> 8;
    const float* sh = ada + (size_t)b*adaStride + shOff;
    const float* sc = ada + (size_t)b*adaStride + scOff;
    float* orow = out + (size_t)t*DD;
    orow[tid]     = (x0-m)*rr*(1.f+sc[tid])     + sh[tid];
    orow[tid+256] = (x1-m)*rr*(1.f+sc[tid+256]) + sh[tid+256];
    orow[tid+512] = (x2-m)*rr*(1.f+sc[tid+512]) + sh[tid+512];
}

__global__ void softmax_k(float* __restrict__ attn){
    const int warp = threadIdx.x>>5, lane = threadIdx.x&31;
    const size_t row = (size_t)blockIdx.x*8 + warp;
    float* p = attn + row*NP;
    float v[8];
#pragma unroll
    for (int j = 0; j < 8; j++) v[j] = p[lane + j*32];
    float mx = v[0];
#pragma unroll
    for (int j = 1; j < 8; j++) mx = fmaxf(mx, v[j]);
#pragma unroll
    for (int o = 16; o; o >>= 1) mx = fmaxf(mx, __shfl_xor_sync(0xffffffffu, mx, o));
    float s = 0.f;
#pragma unroll
    for (int j = 0; j < 8; j++){ v[j] = expf(v[j]-mx); s += v[j]; }
#pragma unroll
    for (int o = 16; o; o >>= 1) s += __shfl_xor_sync(0xffffffffu, s, o);
    const float inv = 1.f/s;
#pragma unroll
    for (int j = 0; j < 8; j++) p[lane + j*32] = v[j]*inv;
}

// ---------------- final head + unpatchify ----------------
__global__ void final_k(const float* __restrict__ hmod, const float* __restrict__ w,
                        const float* __restrict__ bias, float* __restrict__ out){
    __shared__ float row[768];
    __shared__ float red[128];
    const int t = blockIdx.x, tid = threadIdx.x;  // 128 threads
#pragma unroll
    for (int rr = 0; rr < 6; rr++) row[tid + rr*128] = hmod[(size_t)t*DD + tid + rr*128];
    __syncthreads();
    const int j = tid & 15, p = tid >> 4;
    float s = 0.f;
#pragma unroll 8
    for (int k = p*96; k < p*96 + 96; ++k) s = fmaf(row[k], w[k*16 + j], s);
    red[tid] = s;
    __syncthreads();
    if (tid < 16){
        float tot = bias[tid];
#pragma unroll
        for (int q = 0; q < 8; q++) tot += red[q*16 + tid];
        const int b = t>>8, n = t&255, gy = n>>4, gx = n&15;
        const int c = tid&3, pq = tid>>2, p1 = pq>>1, p2 = pq&1;
        out[((b*4+c)*32 + gy*2+p1)*32 + gx*2+p2] = tot;
    }
}

// ---------------- host launcher ----------------
extern "C" void kernel_launch(void* const* d_in, const int* in_sizes, int n_in,
                              void* d_out, int out_size){
    (void)in_sizes; (void)n_in; (void)out_size;
    const float* x     = (const float*)d_in[0];
    const float* tt    = (const float*)d_in[1];
    const float* convw = (const float*)d_in[2];
    const float* convb = (const float*)d_in[3];
    const float* tw1   = (const float*)d_in[4];
    const float* tb1   = (const float*)d_in[5];
    const float* tw2   = (const float*)d_in[6];
    const float* tb2   = (const float*)d_in[7];
    const float* cls   = (const float*)d_in[8];
    const float* qkvw  = (const float*)d_in[9];
    const float* qkvb  = (const float*)d_in[10];
    const float* ow    = (const float*)d_in[11];
    const float* ob    = (const float*)d_in[12];
    const float* aw    = (const float*)d_in[13];
    const float* ab    = (const float*)d_in[14];
    const float* m1w   = (const float*)d_in[15];
    const float* m1b   = (const float*)d_in[16];
    const float* m2w   = (const float*)d_in[17];
    const float* m2b   = (const float*)d_in[18];
    const float* faw   = (const float*)d_in[19];
    const float* fab   = (const float*)d_in[20];
    const float* flw   = (const float*)d_in[21];
    const float* flb   = (const float*)d_in[22];
    const int*   lab   = (const int*)d_in[23];
    float* out = (float*)d_out;

    float *tok,*hmod,*o,*qkv,*attn,*hmid,*c0,*tmid,*c,*sc,*ada,*adaf;
    float *qkvwT,*owT,*m1wT,*m2wT,*awT,*tw1T,*tw2T,*fawT;
    cudaGetSymbolAddress((void**)&tok,  g_tok);
    cudaGetSymbolAddress((void**)&hmod, g_hmod);
    cudaGetSymbolAddress((void**)&o,    g_o);
    cudaGetSymbolAddress((void**)&qkv,  g_qkv);
    cudaGetSymbolAddress((void**)&attn, g_attn);
    cudaGetSymbolAddress((void**)&hmid, g_hmid);
    cudaGetSymbolAddress((void**)&c0,   g_c0);
    cudaGetSymbolAddress((void**)&tmid, g_tmid);
    cudaGetSymbolAddress((void**)&c,    g_c);
    cudaGetSymbolAddress((void**)&sc,   g_sc);
    cudaGetSymbolAddress((void**)&ada,  g_ada);
    cudaGetSymbolAddress((void**)&adaf, g_adaf);
    cudaGetSymbolAddress((void**)&qkvwT,g_qkvwT);
    cudaGetSymbolAddress((void**)&owT,  g_owT);
    cudaGetSymbolAddress((void**)&m1wT, g_m1wT);
    cudaGetSymbolAddress((void**)&m2wT, g_m2wT);
    cudaGetSymbolAddress((void**)&awT,  g_awT);
    cudaGetSymbolAddress((void**)&tw1T, g_tw1T);
    cudaGetSymbolAddress((void**)&tw2T, g_tw2T);
    cudaGetSymbolAddress((void**)&fawT, g_fawT);

    cudaFuncSetAttribute(gemm_tc<0>, cudaFuncAttributeMaxDynamicSharedMemorySize, GTC_SMEM);
    cudaFuncSetAttribute(gemm_tc<1>, cudaFuncAttributeMaxDynamicSharedMemorySize, GTC_SMEM);
    cudaFuncSetAttribute(gemm_tc<2>, cudaFuncAttributeMaxDynamicSharedMemorySize, GTC_SMEM);
    cudaFuncSetAttribute(gemm_tc<3>, cudaFuncAttributeMaxDynamicSharedMemorySize, GTC_SMEM);
    cudaFuncSetAttribute(gemm_tc<4>, cudaFuncAttributeMaxDynamicSharedMemorySize, GTC_SMEM);
    cudaFuncSetAttribute(scores_tc,  cudaFuncAttributeMaxDynamicSharedMemorySize, SC_SMEM);
    cudaFuncSetAttribute(attnv_tc,   cudaFuncAttributeMaxDynamicSharedMemorySize, AV_SMEM);

    // weight transposes [K,N] -> [N,K]
    transpose_k<<<dim3(HID/32, DD/32, 1),  256>>>(tw1,  tw1T, DD,  HID);
    transpose_k<<<dim3(DD/32,  HID/32, 1), 256>>>(tw2,  tw2T, HID, DD);
    transpose_k<<<dim3(2*DD/32, DD/32, 1), 256>>>(faw,  fawT, DD,  2*DD);
    transpose_k<<<dim3(3*DD/32, DD/32, LL),256>>>(qkvw, qkvwT,DD,  3*DD);
    transpose_k<<<dim3(DD/32,  DD/32, LL), 256>>>(ow,   owT,  DD,  DD);
    transpose_k<<<dim3(6*DD/32, DD/32, LL),256>>>(aw,   awT,  DD,  6*DD);
    transpose_k<<<dim3(HID/32, DD/32, LL), 256>>>(m1w,  m1wT, DD,  HID);
    transpose_k<<<dim3(DD/32,  HID/32, LL),256>>>(m2w,  m2wT, HID, DD);

    patchify_k<<<TT, 256>>>(x, convw, convb, tok);
    time_embed_k<<<BB, 384>>>(tt, c0);

    // conditioning: tmlp1 (silu), tmlp2 (+cls), silu(c), batched adaLN
    gemm_tc<3><<<dim3(HID/128, 1, 1), 256, GTC_SMEM>>>(c0, tw1T, tb1, tmid,
        32, HID, DD, nullptr, 0, nullptr, 0, 0, 0);
    gemm_tc<4><<<dim3(DD/128, 1, 1), 256, GTC_SMEM>>>(tmid, tw2T, tb2, c,
        32, DD, HID, cls, 0, lab, 0, 0, 0);
    silu_k<<<(BB*DD + 255)/256, 256>>>(c, sc, BB*DD);
    gemm_tc<0><<<dim3(6*DD/128, 1, LL), 256, GTC_SMEM>>>(sc, awT, ab, ada,
        32, 6*DD, DD, nullptr, 0, nullptr,
        (long long)6*DD*DD, (long long)6*DD, (long long)BB*6*DD);

    for (int i = 0; i < LL; i++){
        const float* adaL = ada + (size_t)i*BB*6*DD;
        // attention branch
        ln_mod_k<<<TT, 256>>>(tok, adaL, 6*DD, 0, DD, hmod);
        gemm_tc<0><<<dim3(3*DD/128, TT/128, 1), 256, GTC_SMEM>>>(hmod,
            qkvwT + (size_t)i*3*DD*DD, qkvb + (size_t)i*3*DD, qkv,
            TT, 3*DD, DD, nullptr, 0, nullptr, 0, 0, 0);
        scores_tc<<<dim3(2, 2, BHH), 256, SC_SMEM>>>(qkv, attn);
        softmax_k<<<(BHH*NP)/8, 256>>>(attn);
        attnv_tc<<<dim3(2, BHH), 256, AV_SMEM>>>(attn, qkv, o);
        gemm_tc<2><<<dim3(DD/128, TT/128, 1), 256, GTC_SMEM>>>(o,
            owT + (size_t)i*DD*DD, ob + (size_t)i*DD, tok,
            TT, DD, DD, adaL, 2*DD, nullptr, 0, 0, 0);
        // mlp branch
        ln_mod_k<<<TT, 256>>>(tok, adaL, 6*DD, 3*DD, 4*DD, hmod);
        gemm_tc<1><<<dim3(HID/128, TT/128, 1), 256, GTC_SMEM>>>(hmod,
            m1wT + (size_t)i*HID*DD, m1b + (size_t)i*HID, hmid,
            TT, HID, DD, nullptr, 0, nullptr, 0, 0, 0);
        gemm_tc<2><<<dim3(DD/128, TT/128, 1), 256, GTC_SMEM>>>(hmid,
            m2wT + (size_t)i*DD*HID, m2b + (size_t)i*DD, tok,
            TT, DD, HID, adaL, 5*DD, nullptr, 0, 0, 0);
    }

    gemm_tc<0><<<dim3(2*DD/128, 1, 1), 256, GTC_SMEM>>>(sc, fawT, fab, adaf,
        32, 2*DD, DD, nullptr, 0, nullptr, 0, 0, 0);
    ln_mod_k<<<TT, 256>>>(tok, adaf, 2*DD, 0, DD, hmod);
    final_k<<<TT, 128>>>(hmod, flw, flb, out);
}

// round 6
// speedup vs baseline: 1.9603x; 1.1032x over previous
#include <cuda_runtime.h>
#include <cuda_bf16.h>
#include <math.h>
#include <stdint.h>

#define BB   32
#define DD   768
#define LL   12
#define HID  3072
#define NP   256
#define TT   8192
#define BHH  384

typedef __nv_bfloat16 bf16;

// ---------------- scratch (static device allocations) ----------------
__device__ float g_tok [TT*DD];
__device__ float g_attn[(size_t)BHH*NP*NP];
__device__ float g_c   [BB*DD];
__device__ float g_ada [LL*BB*6*DD];
__device__ float g_adaf[BB*2*DD];
// split activations (hi/lo bf16)
__device__ bf16 g_hmodh[TT*DD],  g_hmodl[TT*DD];
__device__ bf16 g_qkvh[(size_t)TT*3*DD], g_qkvl[(size_t)TT*3*DD];
__device__ bf16 g_ph[(size_t)BHH*NP*NP], g_pl[(size_t)BHH*NP*NP];
__device__ bf16 g_oh[TT*DD], g_ol[TT*DD];
__device__ bf16 g_hmidh[(size_t)TT*HID], g_hmidl[(size_t)TT*HID];
__device__ bf16 g_c0h[256*DD], g_c0l[256*DD];           // padded to 256 rows
__device__ bf16 g_tmidh[(size_t)256*HID], g_tmidl[(size_t)256*HID];
__device__ bf16 g_sch[256*DD], g_scl[256*DD];
// split transposed weights [N][K]
__device__ bf16 g_qkvwh[(size_t)LL*3*DD*DD], g_qkvwl[(size_t)LL*3*DD*DD];
__device__ bf16 g_owh[(size_t)LL*DD*DD],     g_owl[(size_t)LL*DD*DD];
__device__ bf16 g_m1wh[(size_t)LL*HID*DD],   g_m1wl[(size_t)LL*HID*DD];
__device__ bf16 g_m2wh[(size_t)LL*DD*HID],   g_m2wl[(size_t)LL*DD*HID];
__device__ bf16 g_awh[(size_t)LL*6*DD*DD],   g_awl[(size_t)LL*6*DD*DD];
__device__ bf16 g_tw1h[(size_t)HID*DD], g_tw1l[(size_t)HID*DD];
__device__ bf16 g_tw2h[(size_t)DD*HID], g_tw2l[(size_t)DD*HID];
__device__ bf16 g_fawh[(size_t)2*DD*DD], g_fawl[(size_t)2*DD*DD];

// ---------------- helpers ----------------
__device__ __forceinline__ uint32_t sm32(const void* p){
    uint32_t a;
    asm("{ .reg .u64 t; cvta.to.shared.u64 t, %1; cvt.u32.u64 %0, t; }" : "=r"(a) : "l"(p));
    return a;
}
__device__ __forceinline__ void cp16(uint32_t dst, const void* src){
    asm volatile("cp.async.cg.shared.global [%0], [%1], 16;" :: "r"(dst), "l"(src) : "memory");
}
__device__ __forceinline__ void ldsm4(uint32_t* r, uint32_t addr){
    asm volatile("ldmatrix.sync.aligned.m8n8.x4.shared.b16 {%0,%1,%2,%3}, [%4];"
        : "=r"(r[0]), "=r"(r[1]), "=r"(r[2]), "=r"(r[3]) : "r"(addr));
}
__device__ __forceinline__ void mma16816(float* d, const uint32_t* a, uint32_t b0, uint32_t b1){
    asm volatile("mma.sync.aligned.m16n8k16.row.col.f32.bf16.bf16.f32 "
        "{%0,%1,%2,%3}, {%4,%5,%6,%7}, {%8,%9}, {%0,%1,%2,%3};"
        : "+f"(d[0]), "+f"(d[1]), "+f"(d[2]), "+f"(d[3])
        : "r"(a[0]), "r"(a[1]), "r"(a[2]), "r"(a[3]), "r"(b0), "r"(b1));
}
__device__ __forceinline__ void split1(float x, bf16 &h, bf16 &l){
    h = __float2bfloat16(x);
    l = __float2bfloat16(x - __bfloat162float(h));
}
__device__ __forceinline__ uint32_t packbf(bf16 a, bf16 b){
    return (uint32_t)__bfloat16_as_ushort(a) | ((uint32_t)__bfloat16_as_ushort(b) << 16);
}
__device__ __forceinline__ float gelu_f(float x){
    return 0.5f * x * (1.0f + erff(x * 0.7071067811865475f));
}
__device__ __forceinline__ float silu_f(float x){
    return x / (1.f + expf(-x));
}

// ---- bf16x3 K=32 chunk micro-kernel, term-major MMA order for ILP ----
// A rows at oAh/oAl, B rows at oBh/oBl, both row stride RS bytes (bf16 data).
template<int MI, int NPAIRS, int RS>
__device__ __forceinline__ void mma_chunk(uint32_t sb, int oAh, int oAl, int oBh, int oBl,
                                          int mrow0, int ncol0, int lane, float (*d)[4]){
    const int r8 = lane & 7, t1 = (lane >> 3) & 1, t2 = (lane >> 4) & 1;
#pragma unroll
    for (int ks = 0; ks < 2; ++ks){
        uint32_t ah[MI][4], al[MI][4], bh[NPAIRS][4], bl[NPAIRS][4];
        const int keA = ks*16 + t2*8;
        const int keB = ks*16 + t1*8;
#pragma unroll
        for (int mi = 0; mi < MI; ++mi){
            const int row = mrow0 + mi*16 + r8 + t1*8;
            ldsm4(ah[mi], sb + oAh + row*RS + keA*2);
            ldsm4(al[mi], sb + oAl + row*RS + keA*2);
        }
#pragma unroll
        for (int p = 0; p < NPAIRS; ++p){
            const int n = ncol0 + p*16 + r8 + t2*8;
            ldsm4(bh[p], sb + oBh + n*RS + keB*2);
            ldsm4(bl[p], sb + oBl + n*RS + keB*2);
        }
        // term hh
#pragma unroll
        for (int mi = 0; mi < MI; ++mi)
#pragma unroll
            for (int p = 0; p < NPAIRS; ++p){
                mma16816(d[mi*(NPAIRS*2)+p*2],   ah[mi], bh[p][0], bh[p][1]);
                mma16816(d[mi*(NPAIRS*2)+p*2+1], ah[mi], bh[p][2], bh[p][3]);
            }
        // term hl
#pragma unroll
        for (int mi = 0; mi < MI; ++mi)
#pragma unroll
            for (int p = 0; p < NPAIRS; ++p){
                mma16816(d[mi*(NPAIRS*2)+p*2],   ah[mi], bl[p][0], bl[p][1]);
                mma16816(d[mi*(NPAIRS*2)+p*2+1], ah[mi], bl[p][2], bl[p][3]);
            }
        // term lh
#pragma unroll
        for (int mi = 0; mi < MI; ++mi)
#pragma unroll
            for (int p = 0; p < NPAIRS; ++p){
                mma16816(d[mi*(NPAIRS*2)+p*2],   al[mi], bh[p][0], bh[p][1]);
                mma16816(d[mi*(NPAIRS*2)+p*2+1], al[mi], bh[p][2], bh[p][3]);
            }
    }
}

// ---------------- main GEMM: out[M,N] = A[M,K] @ W[N,K]^T, bf16x3 ----------
// 256x128 CTA tile, 8 warps of 64x64, 3-stage cp.async.
// stage layout: Ah@0 (256x80=20480), Al@20480, Bh@40960 (128x80=10240), Bl@51200
#define STG_BYTES 61440
#define GTC_SMEM  (3*STG_BYTES)
// EPI: 0 fp32 | 1 gelu+split | 2 gated residual fp32 | 3 silu+split | 4 +cls fp32 | 5 split
template<int EPI>
__global__ void __launch_bounds__(256) gemm_tc(
    const bf16* __restrict__ Ah, const bf16* __restrict__ Al, int lda,
    const bf16* __restrict__ Wh, const bf16* __restrict__ Wl,
    const float* __restrict__ bias,
    float* __restrict__ outF, bf16* __restrict__ outH, bf16* __restrict__ outL,
    int Mvalid, int N, int K,
    const float* __restrict__ aux, int auxOff, const int* __restrict__ lab,
    long long wz, long long bz, long long oz)
{
    extern __shared__ char smem[];
    const uint32_t sb = sm32(smem);
    const int tid = threadIdx.x, lane = tid & 31, wid = tid >> 5;
    const int warpM = wid & 3, warpN = wid >> 2;
    const int m0 = blockIdx.y*256, n0 = blockIdx.x*128, z = blockIdx.z;
    const bf16* WhZ = Wh + (size_t)z*wz;
    const bf16* WlZ = Wl + (size_t)z*wz;
    const float* BzP = bias + (size_t)z*bz;

    float d[32][4];
#pragma unroll
    for (int i = 0; i < 32; ++i)
#pragma unroll
        for (int j = 0; j < 4; ++j) d[i][j] = 0.f;

    auto issue = [&](int s, int t){
        const int kt = t << 5;
        const uint32_t base = sb + s*STG_BYTES;
#pragma unroll
        for (int it = 0; it < 4; ++it){
            const int idx = tid + it*256;            // 0..1023
            const int row = idx >> 2, q = idx & 3;
            const uint32_t dst = base + row*80 + q*16;
            cp16(dst,         (const char*)(Ah + (size_t)(m0+row)*lda + kt) + q*16);
            cp16(dst + 20480, (const char*)(Al + (size_t)(m0+row)*lda + kt) + q*16);
        }
#pragma unroll
        for (int it = 0; it < 2; ++it){
            const int idx = tid + it*256;            // 0..511
            const int row = idx >> 2, q = idx & 3;
            const uint32_t dst = base + 40960 + row*80 + q*16;
            cp16(dst,         (const char*)(WhZ + (size_t)(n0+row)*K + kt) + q*16);
            cp16(dst + 10240, (const char*)(WlZ + (size_t)(n0+row)*K + kt) + q*16);
        }
        asm volatile("cp.async.commit_group;" ::: "memory");
    };

    const int nk = K >> 5;
    issue(0, 0); issue(1, 1);
    int stage = 0;
    for (int t = 0; t < nk; ++t){
        asm volatile("cp.async.wait_group 1;" ::: "memory");
        __syncthreads();
        if (t + 2 < nk) issue((stage + 2) % 3, t + 2);
        else asm volatile("cp.async.commit_group;" ::: "memory");
        mma_chunk<4,4,80>(sb + stage*STG_BYTES, 0, 20480, 40960, 51200,
                          warpM*64, warpN*64, lane, d);
        stage = (stage + 1) % 3;
    }

    const int g = lane >> 2, tig = lane & 3;
#pragma unroll
    for (int mi = 0; mi < 4; ++mi){
#pragma unroll
        for (int ni = 0; ni < 8; ++ni){
            const int n = n0 + warpN*64 + ni*8 + tig*2;
            const float2 bv = *(const float2*)(BzP + n);
#pragma unroll
            for (int hr = 0; hr < 2; ++hr){
                const int m = m0 + warpM*64 + mi*16 + g + hr*8;
                if (m < Mvalid){
                    float x0 = d[mi*8+ni][hr*2+0] + bv.x;
                    float x1 = d[mi*8+ni][hr*2+1] + bv.y;
                    const size_t oi = (size_t)m*N + n;
                    if (EPI == 0){
                        *(float2*)(outF + (size_t)z*oz + oi) = make_float2(x0, x1);
                    } else if (EPI == 2){
                        const float2 gv = *(const float2*)(aux + (size_t)(m>>8)*(6*DD) + auxOff + n);
                        float2 ov = *(float2*)(outF + oi);
                        *(float2*)(outF + oi) = make_float2(ov.x + gv.x*x0, ov.y + gv.y*x1);
                    } else if (EPI == 4){
                        const float2 cv = *(const float2*)(aux + (size_t)lab[m]*DD + n);
                        *(float2*)(outF + oi) = make_float2(x0 + cv.x, x1 + cv.y);
                    } else {
                        if (EPI == 1){ x0 = gelu_f(x0); x1 = gelu_f(x1); }
                        if (EPI == 3){ x0 = silu_f(x0); x1 = silu_f(x1); }
                        bf16 h0, l0, h1, l1;
                        split1(x0, h0, l0); split1(x1, h1, l1);
                        *(uint32_t*)(outH + oi) = packbf(h0, h1);
                        *(uint32_t*)(outL + oi) = packbf(l0, l1);
                    }
                }
            }
        }
    }
}

// ---------------- attention scores: S = Q @ K^T * 0.125 ----------
// smem: Qh@0, Ql@18432, Kh@36864, Kl@55296; 128 rows x 144B stride (64 bf16 payload x2 halves)
#define SC_SMEM 73728
__global__ void __launch_bounds__(256) scores_tc(const bf16* __restrict__ qh,
                                                 const bf16* __restrict__ ql,
                                                 float* __restrict__ attn){
    extern __shared__ char smem[];
    const uint32_t sb = sm32(smem);
    const int tid = threadIdx.x, lane = tid & 31, wid = tid >> 5;
    const int warpM = wid & 1, warpN = wid >> 1;
    const int z = blockIdx.z, b = z/12, h = z%12;
    const int m0 = blockIdx.y*128, n0 = blockIdx.x*128;
    const size_t qbase = (size_t)b*NP*2304 + h*64;

    float d[16][4];
#pragma unroll
    for (int i = 0; i < 16; ++i)
#pragma unroll
        for (int j = 0; j < 4; ++j) d[i][j] = 0.f;

    const int lrow = tid >> 1, lq = tid & 1;
    const int sOff = lrow*144 + lq*64;
    const size_t qr = qbase + (size_t)(m0+lrow)*2304 + lq*32;
    const size_t kr = qbase + 768 + (size_t)(n0+lrow)*2304 + lq*32;
#pragma unroll
    for (int j = 0; j < 4; ++j){
        *(uint4*)(smem + sOff + j*16)         = *(const uint4*)(qh + qr + j*8);
        *(uint4*)(smem + 18432 + sOff + j*16) = *(const uint4*)(ql + qr + j*8);
        *(uint4*)(smem + 36864 + sOff + j*16) = *(const uint4*)(qh + kr + j*8);
        *(uint4*)(smem + 55296 + sOff + j*16) = *(const uint4*)(ql + kr + j*8);
    }
    __syncthreads();
    mma_chunk<4,2,144>(sb, 0,    18432,    36864,    55296,    warpM*64, warpN*32, lane, d);
    mma_chunk<4,2,144>(sb, 64,   18432+64, 36864+64, 55296+64, warpM*64, warpN*32, lane, d);

    const int g = lane >> 2, tig = lane & 3;
    float* ap = attn + (size_t)z*NP*NP;
#pragma unroll
    for (int mi = 0; mi < 4; ++mi)
#pragma unroll
        for (int ni = 0; ni < 4; ++ni){
            const int n = n0 + warpN*32 + ni*8 + tig*2;
            const int m = m0 + warpM*64 + mi*16 + g;
            *(float2*)(ap + (size_t)m*NP + n) =
                make_float2(d[mi*4+ni][0]*0.125f, d[mi*4+ni][1]*0.125f);
            *(float2*)(ap + (size_t)(m+8)*NP + n) =
                make_float2(d[mi*4+ni][2]*0.125f, d[mi*4+ni][3]*0.125f);
        }
}

// ---------------- attention AV: O = P @ V, split output ----------
// stage (30720B): Ph@0 (128x80), Pl@10240, Vh@20480 (64x80), Vl@25600
#define AV_SMEM 61440
__global__ void __launch_bounds__(256) attnv_tc(const bf16* __restrict__ ph,
                                                const bf16* __restrict__ pl,
                                                const bf16* __restrict__ qh,
                                                const bf16* __restrict__ ql,
                                                bf16* __restrict__ oh,
                                                bf16* __restrict__ ol){
    extern __shared__ char smem[];
    const uint32_t sb = sm32(smem);
    const int tid = threadIdx.x, lane = tid & 31, wid = tid >> 5;
    const int warpM = wid & 3, warpN = wid >> 2;
    const int z = blockIdx.y, b = z/12, h = z%12;
    const int m0 = blockIdx.x*128;
    const bf16* Ph = ph + (size_t)z*NP*NP;
    const bf16* Pl = pl + (size_t)z*NP*NP;
    const size_t vbase = (size_t)b*NP*2304 + 1536 + h*64;

    float d[8][4];
#pragma unroll
    for (int i = 0; i < 8; ++i)
#pragma unroll
        for (int j = 0; j < 4; ++j) d[i][j] = 0.f;

    const int lrow = tid >> 1, lq = tid & 1;
    const int sOffA = lrow*80 + lq*32;
    const int vk = tid >> 3, vn8 = tid & 7;

    auto loadP = [&](int kt, uint4* rh, uint4* rl){
        const size_t src = (size_t)(m0+lrow)*NP + kt + lq*16;
#pragma unroll
        for (int j = 0; j < 2; ++j){
            rh[j] = *(const uint4*)(Ph + src + j*8);
            rl[j] = *(const uint4*)(Pl + src + j*8);
        }
    };
    auto loadV = [&](int kt, uint32_t* vh, uint32_t* vl){
        const size_t src = vbase + (size_t)(kt+vk)*2304 + vn8*8;
#pragma unroll
        for (int w = 0; w < 4; ++w){
            vh[w] = *(const uint32_t*)(qh + src + w*2);
            vl[w] = *(const uint32_t*)(ql + src + w*2);
        }
    };
    auto store = [&](char* base, const uint4* rh, const uint4* rl,
                     const uint32_t* vh, const uint32_t* vl){
#pragma unroll
        for (int j = 0; j < 2; ++j){
            *(uint4*)(base + sOffA + j*16)         = rh[j];
            *(uint4*)(base + 10240 + sOffA + j*16) = rl[j];
        }
#pragma unroll
        for (int w = 0; w < 4; ++w){
            const int dc = vn8*8 + w*2;
            *(bf16*)(base + 20480 + dc*80 + vk*2)     = __ushort_as_bfloat16((unsigned short)(vh[w] & 0xffff));
            *(bf16*)(base + 20480 + (dc+1)*80 + vk*2) = __ushort_as_bfloat16((unsigned short)(vh[w] >> 16));
            *(bf16*)(base + 25600 + dc*80 + vk*2)     = __ushort_as_bfloat16((unsigned short)(vl[w] & 0xffff));
            *(bf16*)(base + 25600 + (dc+1)*80 + vk*2) = __ushort_as_bfloat16((unsigned short)(vl[w] >> 16));
        }
    };

    {
        uint4 rh[2], rl[2]; uint32_t vh[4], vl[4];
        loadP(0, rh, rl); loadV(0, vh, vl);
        store(smem, rh, rl, vh, vl);
    }
    __syncthreads();

    for (int t = 0; t < 8; ++t){
        uint4 rh[2], rl[2]; uint32_t vh[4], vl[4];
        const bool pf = (t + 1 < 8);
        if (pf){ loadP((t+1)*32, rh, rl); loadV((t+1)*32, vh, vl); }
        mma_chunk<2,2,80>(sb + (uint32_t)(t&1)*30720u, 0, 10240, 20480, 25600,
                          warpM*32, warpN*32, lane, d);
        if (pf) store(smem + ((t+1)&1)*30720, rh, rl, vh, vl);
        __syncthreads();
    }

    const int g = lane >> 2, tig = lane & 3;
#pragma unroll
    for (int mi = 0; mi < 2; ++mi)
#pragma unroll
        for (int ni = 0; ni < 4; ++ni){
            const int dc = warpN*32 + ni*8 + tig*2;
#pragma unroll
            for (int hr = 0; hr < 2; ++hr){
                const int m = m0 + warpM*32 + mi*16 + g + hr*8;
                const size_t oi = (size_t)(b*NP + m)*DD + h*64 + dc;
                bf16 h0, l0, h1, l1;
                split1(d[mi*4+ni][hr*2+0], h0, l0);
                split1(d[mi*4+ni][hr*2+1], h1, l1);
                *(uint32_t*)(oh + oi) = packbf(h0, h1);
                *(uint32_t*)(ol + oi) = packbf(l0, l1);
            }
        }
}

// ---------------- weight transpose + split: in[K,N] -> outh/outl [N,K] ----------
__global__ void transpose_split(const float* __restrict__ in, bf16* __restrict__ oh,
                                bf16* __restrict__ ol, int K, int N){
    __shared__ float tile[32][33];
    const size_t zoff = (size_t)blockIdx.z * K * N;
    const float* inz = in + zoff;
    const int n0 = blockIdx.x*32, k0 = blockIdx.y*32;
    const int lx = threadIdx.x & 31, ly = threadIdx.x >> 5;
#pragma unroll
    for (int rr = 0; rr < 32; rr += 8)
        tile[ly+rr][lx] = inz[(size_t)(k0+ly+rr)*N + n0+lx];
    __syncthreads();
#pragma unroll
    for (int rr = 0; rr < 32; rr += 8){
        float v = tile[lx][ly+rr];
        bf16 h, l; split1(v, h, l);
        const size_t oi = zoff + (size_t)(n0+ly+rr)*K + k0+lx;
        oh[oi] = h; ol[oi] = l;
    }
}

// ---------------- elementwise / embedding ----------------
__global__ void silu_split_k(const float* __restrict__ in, bf16* __restrict__ oh,
                             bf16* __restrict__ ol, int n){
    int i = blockIdx.x*256 + threadIdx.x;
    if (i < n){
        float v = silu_f(in[i]);
        bf16 h, l; split1(v, h, l);
        oh[i] = h; ol[i] = l;
    }
}

__global__ void time_embed_k(const float* __restrict__ t, bf16* __restrict__ oh,
                             bf16* __restrict__ ol){
    int b = blockIdx.x, j = threadIdx.x;  // 384 threads
    float e = t[b] * expf(-(float)j * (9.210340371976184f / 383.f));
    bf16 h, l;
    split1(sinf(e), h, l); oh[b*DD + j] = h;       ol[b*DD + j] = l;
    split1(cosf(e), h, l); oh[b*DD + 384 + j] = h; ol[b*DD + 384 + j] = l;
}

__global__ void patchify_k(const float* __restrict__ x, const float* __restrict__ cw,
                           const float* __restrict__ cb, float* __restrict__ tok){
    __shared__ float xv[16];
    const int t = blockIdx.x, tid = threadIdx.x;
    const int b = t>>8, n = t&255, gy = n>>4, gx = n&15;
    if (tid < 16){
        int c = tid>>2, p1 = (tid>>1)&1, p2 = tid&1;
        xv[tid] = x[((b*4+c)*32 + gy*2+p1)*32 + gx*2+p2];
    }
    __syncthreads();
    for (int d = tid; d < DD; d += 256){
        const float4* w4 = (const float4*)(cw + d*16);
        float s = cb[d];
#pragma unroll
        for (int q = 0; q < 4; q++){
            float4 w = w4[q];
            s += xv[q*4+0]*w.x + xv[q*4+1]*w.y + xv[q*4+2]*w.z + xv[q*4+3]*w.w;
        }
        int i2 = d & ~1;
        float ang = (float)n * expf(-(float)i2 * (9.210340371976184f / 768.f));
        float pe = (d & 1) ? cosf(ang) : sinf(ang);
        tok[(size_t)t*DD + d] = s + pe;
    }
}

__global__ void ln_mod_k(const float* __restrict__ in, const float* __restrict__ ada,
                         int adaStride, int shOff, int scOff,
                         bf16* __restrict__ outH, bf16* __restrict__ outL){
    const int t = blockIdx.x, tid = threadIdx.x;
    const float* row = in + (size_t)t*DD;
    float x0 = row[tid], x1 = row[tid+256], x2 = row[tid+512];
    float sum = x0 + x1 + x2;
    float sq  = fmaf(x0,x0, fmaf(x1,x1, x2*x2));
    __shared__ float s1[8], s2[8];
#pragma unroll
    for (int o = 16; o; o >>= 1){
        sum += __shfl_xor_sync(0xffffffffu, sum, o);
        sq  += __shfl_xor_sync(0xffffffffu, sq,  o);
    }
    if ((tid & 31) == 0){ s1[tid>>5] = sum; s2[tid>>5] = sq; }
    __syncthreads();
    float tot = 0.f, totq = 0.f;
#pragma unroll
    for (int w = 0; w < 8; w++){ tot += s1[w]; totq += s2[w]; }
    float m   = tot * (1.f/768.f);
    float var = totq * (1.f/768.f) - m*m;
    float rr  = rsqrtf(var + 1e-6f);
    const int b = t >> 8;
    const float* sh = ada + (size_t)b*adaStride + shOff;
    const float* sc = ada + (size_t)b*adaStride + scOff;
    const size_t o0 = (size_t)t*DD;
    float ys[3] = {
        (x0-m)*rr*(1.f+sc[tid])     + sh[tid],
        (x1-m)*rr*(1.f+sc[tid+256]) + sh[tid+256],
        (x2-m)*rr*(1.f+sc[tid+512]) + sh[tid+512]
    };
#pragma unroll
    for (int p = 0; p < 3; ++p){
        bf16 h, l; split1(ys[p], h, l);
        outH[o0 + tid + p*256] = h;
        outL[o0 + tid + p*256] = l;
    }
}

__global__ void softmax_k(const float* __restrict__ attn, bf16* __restrict__ ph,
                          bf16* __restrict__ pl){
    const int warp = threadIdx.x>>5, lane = threadIdx.x&31;
    const size_t row = (size_t)blockIdx.x*8 + warp;
    const float* p = attn + row*NP;
    float v[8];
#pragma unroll
    for (int j = 0; j < 8; j++) v[j] = p[lane + j*32];
    float mx = v[0];
#pragma unroll
    for (int j = 1; j < 8; j++) mx = fmaxf(mx, v[j]);
#pragma unroll
    for (int o = 16; o; o >>= 1) mx = fmaxf(mx, __shfl_xor_sync(0xffffffffu, mx, o));
    float s = 0.f;
#pragma unroll
    for (int j = 0; j < 8; j++){ v[j] = expf(v[j]-mx); s += v[j]; }
#pragma unroll
    for (int o = 16; o; o >>= 1) s += __shfl_xor_sync(0xffffffffu, s, o);
    const float inv = 1.f/s;
#pragma unroll
    for (int j = 0; j < 8; j++){
        bf16 h, l; split1(v[j]*inv, h, l);
        ph[row*NP + lane + j*32] = h;
        pl[row*NP + lane + j*32] = l;
    }
}

// ---------------- final head + unpatchify ----------------
__global__ void final_k(const bf16* __restrict__ hmodh, const bf16* __restrict__ hmodl,
                        const float* __restrict__ w, const float* __restrict__ bias,
                        float* __restrict__ out){
    __shared__ float row[768];
    __shared__ float red[128];
    const int t = blockIdx.x, tid = threadIdx.x;  // 128 threads
#pragma unroll
    for (int rr = 0; rr < 6; rr++){
        const size_t i = (size_t)t*DD + tid + rr*128;
        row[tid + rr*128] = __bfloat162float(hmodh[i]) + __bfloat162float(hmodl[i]);
    }
    __syncthreads();
    const int j = tid & 15, p = tid >> 4;
    float s = 0.f;
#pragma unroll 8
    for (int k = p*96; k < p*96 + 96; ++k) s = fmaf(row[k], w[k*16 + j], s);
    red[tid] = s;
    __syncthreads();
    if (tid < 16){
        float tot = bias[tid];
#pragma unroll
        for (int q = 0; q < 8; q++) tot += red[q*16 + tid];
        const int b = t>>8, n = t&255, gy = n>>4, gx = n&15;
        const int c = tid&3, pq = tid>>2, p1 = pq>>1, p2 = pq&1;
        out[((b*4+c)*32 + gy*2+p1)*32 + gx*2+p2] = tot;
    }
}

// ---------------- host launcher ----------------
extern "C" void kernel_launch(void* const* d_in, const int* in_sizes, int n_in,
                              void* d_out, int out_size){
    (void)in_sizes; (void)n_in; (void)out_size;
    const float* x     = (const float*)d_in[0];
    const float* tt    = (const float*)d_in[1];
    const float* convw = (const float*)d_in[2];
    const float* convb = (const float*)d_in[3];
    const float* tw1   = (const float*)d_in[4];
    const float* tb1   = (const float*)d_in[5];
    const float* tw2   = (const float*)d_in[6];
    const float* tb2   = (const float*)d_in[7];
    const float* cls   = (const float*)d_in[8];
    const float* qkvw  = (const float*)d_in[9];
    const float* qkvb  = (const float*)d_in[10];
    const float* ow    = (const float*)d_in[11];
    const float* ob    = (const float*)d_in[12];
    const float* aw    = (const float*)d_in[13];
    const float* ab    = (const float*)d_in[14];
    const float* m1w   = (const float*)d_in[15];
    const float* m1b   = (const float*)d_in[16];
    const float* m2w   = (const float*)d_in[17];
    const float* m2b   = (const float*)d_in[18];
    const float* faw   = (const float*)d_in[19];
    const float* fab   = (const float*)d_in[20];
    const float* flw   = (const float*)d_in[21];
    const float* flb   = (const float*)d_in[22];
    const int*   lab   = (const int*)d_in[23];
    float* out = (float*)d_out;

    float *tok,*attn,*c,*ada,*adaf;
    bf16 *hmodh,*hmodl,*qkvh,*qkvl,*ph,*pl,*oh,*ol,*hmidh,*hmidl;
    bf16 *c0h,*c0l,*tmidh,*tmidl,*sch,*scl;
    bf16 *qkvwh,*qkvwl,*owh,*owl,*m1wh,*m1wl,*m2wh,*m2wl,*awh,*awl;
    bf16 *tw1h,*tw1l,*tw2h,*tw2l,*fawh,*fawl;
    cudaGetSymbolAddress((void**)&tok,  g_tok);
    cudaGetSymbolAddress((void**)&attn, g_attn);
    cudaGetSymbolAddress((void**)&c,    g_c);
    cudaGetSymbolAddress((void**)&ada,  g_ada);
    cudaGetSymbolAddress((void**)&adaf, g_adaf);
    cudaGetSymbolAddress((void**)&hmodh,g_hmodh); cudaGetSymbolAddress((void**)&hmodl,g_hmodl);
    cudaGetSymbolAddress((void**)&qkvh, g_qkvh);  cudaGetSymbolAddress((void**)&qkvl, g_qkvl);
    cudaGetSymbolAddress((void**)&ph,   g_ph);    cudaGetSymbolAddress((void**)&pl,   g_pl);
    cudaGetSymbolAddress((void**)&oh,   g_oh);    cudaGetSymbolAddress((void**)&ol,   g_ol);
    cudaGetSymbolAddress((void**)&hmidh,g_hmidh); cudaGetSymbolAddress((void**)&hmidl,g_hmidl);
    cudaGetSymbolAddress((void**)&c0h,  g_c0h);   cudaGetSymbolAddress((void**)&c0l,  g_c0l);
    cudaGetSymbolAddress((void**)&tmidh,g_tmidh); cudaGetSymbolAddress((void**)&tmidl,g_tmidl);
    cudaGetSymbolAddress((void**)&sch,  g_sch);   cudaGetSymbolAddress((void**)&scl,  g_scl);
    cudaGetSymbolAddress((void**)&qkvwh,g_qkvwh); cudaGetSymbolAddress((void**)&qkvwl,g_qkvwl);
    cudaGetSymbolAddress((void**)&owh,  g_owh);   cudaGetSymbolAddress((void**)&owl,  g_owl);
    cudaGetSymbolAddress((void**)&m1wh, g_m1wh);  cudaGetSymbolAddress((void**)&m1wl, g_m1wl);
    cudaGetSymbolAddress((void**)&m2wh, g_m2wh);  cudaGetSymbolAddress((void**)&m2wl, g_m2wl);
    cudaGetSymbolAddress((void**)&awh,  g_awh);   cudaGetSymbolAddress((void**)&awl,  g_awl);
    cudaGetSymbolAddress((void**)&tw1h, g_tw1h);  cudaGetSymbolAddress((void**)&tw1l, g_tw1l);
    cudaGetSymbolAddress((void**)&tw2h, g_tw2h);  cudaGetSymbolAddress((void**)&tw2l, g_tw2l);
    cudaGetSymbolAddress((void**)&fawh, g_fawh);  cudaGetSymbolAddress((void**)&fawl, g_fawl);

    cudaFuncSetAttribute(gemm_tc<0>, cudaFuncAttributeMaxDynamicSharedMemorySize, GTC_SMEM);
    cudaFuncSetAttribute(gemm_tc<1>, cudaFuncAttributeMaxDynamicSharedMemorySize, GTC_SMEM);
    cudaFuncSetAttribute(gemm_tc<2>, cudaFuncAttributeMaxDynamicSharedMemorySize, GTC_SMEM);
    cudaFuncSetAttribute(gemm_tc<3>, cudaFuncAttributeMaxDynamicSharedMemorySize, GTC_SMEM);
    cudaFuncSetAttribute(gemm_tc<4>, cudaFuncAttributeMaxDynamicSharedMemorySize, GTC_SMEM);
    cudaFuncSetAttribute(gemm_tc<5>, cudaFuncAttributeMaxDynamicSharedMemorySize, GTC_SMEM);
    cudaFuncSetAttribute(scores_tc,  cudaFuncAttributeMaxDynamicSharedMemorySize, SC_SMEM);
    cudaFuncSetAttribute(attnv_tc,   cudaFuncAttributeMaxDynamicSharedMemorySize, AV_SMEM);

    // weight transpose + split: [K,N] -> [N,K] hi/lo
    transpose_split<<<dim3(HID/32, DD/32, 1),  256>>>(tw1,  tw1h, tw1l, DD,  HID);
    transpose_split<<<dim3(DD/32,  HID/32, 1), 256>>>(tw2,  tw2h, tw2l, HID, DD);
    transpose_split<<<dim3(2*DD/32, DD/32, 1), 256>>>(faw,  fawh, fawl, DD,  2*DD);
    transpose_split<<<dim3(3*DD/32, DD/32, LL),256>>>(qkvw, qkvwh,qkvwl,DD,  3*DD);
    transpose_split<<<dim3(DD/32,  DD/32, LL), 256>>>(ow,   owh,  owl,  DD,  DD);
    transpose_split<<<dim3(6*DD/32, DD/32, LL),256>>>(aw,   awh,  awl,  DD,  6*DD);
    transpose_split<<<dim3(HID/32, DD/32, LL), 256>>>(m1w,  m1wh, m1wl, DD,  HID);
    transpose_split<<<dim3(DD/32,  HID/32, LL),256>>>(m2w,  m2wh, m2wl, HID, DD);

    patchify_k<<<TT, 256>>>(x, convw, convb, tok);
    time_embed_k<<<BB, 384>>>(tt, c0h, c0l);

    // conditioning
    gemm_tc<3><<<dim3(HID/128, 1, 1), 256, GTC_SMEM>>>(c0h, c0l, DD, tw1h, tw1l, tb1,
        nullptr, tmidh, tmidl, 32, HID, DD, nullptr, 0, nullptr, 0, 0, 0);
    gemm_tc<4><<<dim3(DD/128, 1, 1), 256, GTC_SMEM>>>(tmidh, tmidl, HID, tw2h, tw2l, tb2,
        c, nullptr, nullptr, 32, DD, HID, cls, 0, lab, 0, 0, 0);
    silu_split_k<<<(BB*DD + 255)/256, 256>>>(c, sch, scl, BB*DD);
    gemm_tc<0><<<dim3(6*DD/128, 1, LL), 256, GTC_SMEM>>>(sch, scl, DD, awh, awl, ab,
        ada, nullptr, nullptr, 32, 6*DD, DD, nullptr, 0, nullptr,
        (long long)6*DD*DD, (long long)6*DD, (long long)BB*6*DD);

    for (int i = 0; i < LL; i++){
        const float* adaL = ada + (size_t)i*BB*6*DD;
        // attention branch
        ln_mod_k<<<TT, 256>>>(tok, adaL, 6*DD, 0, DD, hmodh, hmodl);
        gemm_tc<5><<<dim3(3*DD/128, TT/256, 1), 256, GTC_SMEM>>>(hmodh, hmodl, DD,
            qkvwh + (size_t)i*3*DD*DD, qkvwl + (size_t)i*3*DD*DD, qkvb + (size_t)i*3*DD,
            nullptr, qkvh, qkvl, TT, 3*DD, DD, nullptr, 0, nullptr, 0, 0, 0);
        scores_tc<<<dim3(2, 2, BHH), 256, SC_SMEM>>>(qkvh, qkvl, attn);
        softmax_k<<<(BHH*NP)/8, 256>>>(attn, ph, pl);
        attnv_tc<<<dim3(2, BHH), 256, AV_SMEM>>>(ph, pl, qkvh, qkvl, oh, ol);
        gemm_tc<2><<<dim3(DD/128, TT/256, 1), 256, GTC_SMEM>>>(oh, ol, DD,
            owh + (size_t)i*DD*DD, owl + (size_t)i*DD*DD, ob + (size_t)i*DD,
            tok, nullptr, nullptr, TT, DD, DD, adaL, 2*DD, nullptr, 0, 0, 0);
        // mlp branch
        ln_mod_k<<<TT, 256>>>(tok, adaL, 6*DD, 3*DD, 4*DD, hmodh, hmodl);
        gemm_tc<1><<<dim3(HID/128, TT/256, 1), 256, GTC_SMEM>>>(hmodh, hmodl, DD,
            m1wh + (size_t)i*HID*DD, m1wl + (size_t)i*HID*DD, m1b + (size_t)i*HID,
            nullptr, hmidh, hmidl, TT, HID, DD, nullptr, 0, nullptr, 0, 0, 0);
        gemm_tc<2><<<dim3(DD/128, TT/256, 1), 256, GTC_SMEM>>>(hmidh, hmidl, HID,
            m2wh + (size_t)i*DD*HID, m2wl + (size_t)i*DD*HID, m2b + (size_t)i*DD,
            tok, nullptr, nullptr, TT, DD, HID, adaL, 5*DD, nullptr, 0, 0, 0);
    }

    gemm_tc<0><<<dim3(2*DD/128, 1, 1), 256, GTC_SMEM>>>(sch, scl, DD, fawh, fawl, fab,
        adaf, nullptr, nullptr, 32, 2*DD, DD, nullptr, 0, nullptr, 0, 0, 0);
    ln_mod_k<<<TT, 256>>>(tok, adaf, 2*DD, 0, DD, hmodh, hmodl);
    final_k<<<TT, 128>>>(hmodh, hmodl, flw, flb, out);
}

// round 7
// speedup vs baseline: 3.4121x; 1.7406x over previous
#include <cuda_runtime.h>
#include <cuda_fp16.h>
#include <math.h>
#include <stdint.h>

#define BB   32
#define DD   768
#define LL   12
#define HID  3072
#define NP   256
#define TT   8192
#define BHH  384

typedef __half fp16;

// ---------------- scratch (static device allocations) ----------------
__device__ float g_tok [TT*DD];
__device__ float g_attn[(size_t)BHH*NP*NP];
__device__ float g_c   [BB*DD];
__device__ float g_ada [LL*BB*6*DD];
__device__ float g_adaf[BB*2*DD];
// fp16 activations
__device__ fp16 g_hmod[TT*DD];
__device__ fp16 g_qkvh[(size_t)TT*3*DD], g_qkvl[(size_t)TT*3*DD];
__device__ fp16 g_pP[(size_t)BHH*NP*NP];
__device__ fp16 g_oo[TT*DD];
__device__ fp16 g_hmid[(size_t)TT*HID];
__device__ fp16 g_c0 [128*DD];      // rows 32..127 stay zero
__device__ fp16 g_tmid[(size_t)128*HID];
__device__ fp16 g_sc [128*DD];
// split transposed weights [N][K] fp16 hi/lo
__device__ fp16 g_qkvwh[(size_t)LL*3*DD*DD], g_qkvwl[(size_t)LL*3*DD*DD];
__device__ fp16 g_owh[(size_t)LL*DD*DD],     g_owl[(size_t)LL*DD*DD];
__device__ fp16 g_m1wh[(size_t)LL*HID*DD],   g_m1wl[(size_t)LL*HID*DD];
__device__ fp16 g_m2wh[(size_t)LL*DD*HID],   g_m2wl[(size_t)LL*DD*HID];
__device__ fp16 g_awh[(size_t)LL*6*DD*DD],   g_awl[(size_t)LL*6*DD*DD];
__device__ fp16 g_tw1h[(size_t)HID*DD], g_tw1l[(size_t)HID*DD];
__device__ fp16 g_tw2h[(size_t)DD*HID], g_tw2l[(size_t)DD*HID];
__device__ fp16 g_fawh[(size_t)2*DD*DD], g_fawl[(size_t)2*DD*DD];

// ---------------- helpers ----------------
__device__ __forceinline__ uint32_t sm32(const void* p){
    uint32_t a;
    asm("{ .reg .u64 t; cvta.to.shared.u64 t, %1; cvt.u32.u64 %0, t; }" : "=r"(a) : "l"(p));
    return a;
}
__device__ __forceinline__ void cp16(uint32_t dst, const void* src){
    asm volatile("cp.async.cg.shared.global [%0], [%1], 16;" :: "r"(dst), "l"(src) : "memory");
}
__device__ __forceinline__ void ldsm4(uint32_t* r, uint32_t addr){
    asm volatile("ldmatrix.sync.aligned.m8n8.x4.shared.b16 {%0,%1,%2,%3}, [%4];"
        : "=r"(r[0]), "=r"(r[1]), "=r"(r[2]), "=r"(r[3]) : "r"(addr));
}
__device__ __forceinline__ void mmaf16(float* d, const uint32_t* a, uint32_t b0, uint32_t b1){
    asm volatile("mma.sync.aligned.m16n8k16.row.col.f32.f16.f16.f32 "
        "{%0,%1,%2,%3}, {%4,%5,%6,%7}, {%8,%9}, {%0,%1,%2,%3};"
        : "+f"(d[0]), "+f"(d[1]), "+f"(d[2]), "+f"(d[3])
        : "r"(a[0]), "r"(a[1]), "r"(a[2]), "r"(a[3]), "r"(b0), "r"(b1));
}
__device__ __forceinline__ void split1(float x, fp16 &h, fp16 &l){
    h = __float2half_rn(x);
    l = __float2half_rn(x - __half2float(h));
}
__device__ __forceinline__ uint32_t packh(fp16 a, fp16 b){
    return (uint32_t)__half_as_ushort(a) | ((uint32_t)__half_as_ushort(b) << 16);
}
__device__ __forceinline__ float gelu_f(float x){
    return 0.5f * x * (1.0f + erff(x * 0.7071067811865475f));
}
__device__ __forceinline__ float silu_f(float x){
    return x / (1.f + expf(-x));
}

// ---- fp16 2-term K=32 chunk: A plain at oA (stride RSA), B split at oBh/oBl (RSB)
template<int MI, int NPAIRS, int RSA, int RSB>
__device__ __forceinline__ void mma2_chunk(uint32_t sb, int oA, int oBh, int oBl,
                                           int mrow0, int ncol0, int lane, float (*d)[4]){
    const int r8 = lane & 7, t1 = (lane >> 3) & 1, t2 = (lane >> 4) & 1;
#pragma unroll
    for (int ks = 0; ks < 2; ++ks){
        uint32_t a[MI][4], bh[NPAIRS][4], bl[NPAIRS][4];
        const int keA = ks*16 + t2*8;
        const int keB = ks*16 + t1*8;
#pragma unroll
        for (int mi = 0; mi < MI; ++mi)
            ldsm4(a[mi], sb + oA + (mrow0 + mi*16 + r8 + t1*8)*RSA + keA*2);
#pragma unroll
        for (int p = 0; p < NPAIRS; ++p){
            const int n = ncol0 + p*16 + r8 + t2*8;
            ldsm4(bh[p], sb + oBh + n*RSB + keB*2);
            ldsm4(bl[p], sb + oBl + n*RSB + keB*2);
        }
#pragma unroll
        for (int mi = 0; mi < MI; ++mi)
#pragma unroll
            for (int p = 0; p < NPAIRS; ++p){
                mmaf16(d[mi*(NPAIRS*2)+p*2],   a[mi], bh[p][0], bh[p][1]);
                mmaf16(d[mi*(NPAIRS*2)+p*2+1], a[mi], bh[p][2], bh[p][3]);
            }
#pragma unroll
        for (int mi = 0; mi < MI; ++mi)
#pragma unroll
            for (int p = 0; p < NPAIRS; ++p){
                mmaf16(d[mi*(NPAIRS*2)+p*2],   a[mi], bl[p][0], bl[p][1]);
                mmaf16(d[mi*(NPAIRS*2)+p*2+1], a[mi], bl[p][2], bl[p][3]);
            }
    }
}

// ---------------- main GEMM: out[M,N] = A[M,K] @ W[N,K]^T ----------
// 128x128 CTA, 8 warps of 64x32, 3-stage cp.async, 2 CTAs/SM.
// stage (30720B): A@0 (128x80), Bh@10240, Bl@20480
#define STG 30720
#define GSM (3*STG)
// EPI: 0 fp32 | 1 gelu fp16 | 2 gated residual fp32 | 3 silu fp16 | 4 +cls fp32 | 5 fp16 hi+lo
template<int EPI>
__global__ void __launch_bounds__(256, 2) gemm_fp16(
    const fp16* __restrict__ A, int lda,
    const fp16* __restrict__ Wh, const fp16* __restrict__ Wl,
    const float* __restrict__ bias,
    float* __restrict__ outF, fp16* __restrict__ outH, fp16* __restrict__ outL,
    int Mvalid, int N, int K,
    const float* __restrict__ aux, int auxOff, const int* __restrict__ lab,
    long long wz, long long bz, long long oz)
{
    extern __shared__ char smem[];
    const uint32_t sb = sm32(smem);
    const int tid = threadIdx.x, lane = tid & 31, wid = tid >> 5;
    const int warpM = wid & 1, warpN = wid >> 1;
    const int m0 = blockIdx.y*128, n0 = blockIdx.x*128, z = blockIdx.z;
    const fp16* WhZ = Wh + (size_t)z*wz;
    const fp16* WlZ = Wl + (size_t)z*wz;
    const float* BzP = bias + (size_t)z*bz;

    float d[16][4];
#pragma unroll
    for (int i = 0; i < 16; ++i)
#pragma unroll
        for (int j = 0; j < 4; ++j) d[i][j] = 0.f;

    auto issue = [&](int s, int t){
        const int kt = t << 5;
        const uint32_t base = sb + s*STG;
#pragma unroll
        for (int it = 0; it < 2; ++it){
            const int idx = tid + it*256;        // 0..511
            const int row = idx >> 2, q = idx & 3;
            const uint32_t dq = row*80 + q*16;
            cp16(base + dq,         (const char*)(A   + (size_t)(m0+row)*lda + kt) + q*16);
            cp16(base + 10240 + dq, (const char*)(WhZ + (size_t)(n0+row)*K   + kt) + q*16);
            cp16(base + 20480 + dq, (const char*)(WlZ + (size_t)(n0+row)*K   + kt) + q*16);
        }
        asm volatile("cp.async.commit_group;" ::: "memory");
    };

    const int nk = K >> 5;
    issue(0, 0); issue(1, 1);
    int stage = 0;
    for (int t = 0; t < nk; ++t){
        asm volatile("cp.async.wait_group 1;" ::: "memory");
        __syncthreads();
        if (t + 2 < nk) issue((stage + 2) % 3, t + 2);
        else asm volatile("cp.async.commit_group;" ::: "memory");
        mma2_chunk<4,2,80,80>(sb + stage*STG, 0, 10240, 20480,
                              warpM*64, warpN*32, lane, d);
        stage = (stage + 1) % 3;
    }

    const int g = lane >> 2, tig = lane & 3;
#pragma unroll
    for (int mi = 0; mi < 4; ++mi){
#pragma unroll
        for (int ni = 0; ni < 4; ++ni){
            const int n = n0 + warpN*32 + ni*8 + tig*2;
            const float2 bv = *(const float2*)(BzP + n);
#pragma unroll
            for (int hr = 0; hr < 2; ++hr){
                const int m = m0 + warpM*64 + mi*16 + g + hr*8;
                if (m < Mvalid){
                    float x0 = d[mi*4+ni][hr*2+0] + bv.x;
                    float x1 = d[mi*4+ni][hr*2+1] + bv.y;
                    const size_t oi = (size_t)m*N + n;
                    if (EPI == 0){
                        *(float2*)(outF + (size_t)z*oz + oi) = make_float2(x0, x1);
                    } else if (EPI == 2){
                        const float2 gv = *(const float2*)(aux + (size_t)(m>>8)*(6*DD) + auxOff + n);
                        float2 ov = *(float2*)(outF + oi);
                        *(float2*)(outF + oi) = make_float2(ov.x + gv.x*x0, ov.y + gv.y*x1);
                    } else if (EPI == 4){
                        const float2 cv = *(const float2*)(aux + (size_t)lab[m]*DD + n);
                        *(float2*)(outF + oi) = make_float2(x0 + cv.x, x1 + cv.y);
                    } else if (EPI == 5){
                        fp16 h0, l0, h1, l1;
                        split1(x0, h0, l0); split1(x1, h1, l1);
                        *(uint32_t*)(outH + oi) = packh(h0, h1);
                        *(uint32_t*)(outL + oi) = packh(l0, l1);
                    } else {
                        if (EPI == 1){ x0 = gelu_f(x0); x1 = gelu_f(x1); }
                        else         { x0 = silu_f(x0); x1 = silu_f(x1); }
                        *(uint32_t*)(outH + oi) = packh(__float2half_rn(x0), __float2half_rn(x1));
                    }
                }
            }
        }
    }
}

// ---------------- attention scores: S = Q @ K^T * 0.125 ----------
// smem: Q@0 (128x144), Kh@18432, Kl@36864 ; total 55296
#define SC_SMEM 55296
__global__ void __launch_bounds__(256) scores_tc(const fp16* __restrict__ qh,
                                                 const fp16* __restrict__ ql,
                                                 float* __restrict__ attn){
    extern __shared__ char smem[];
    const uint32_t sb = sm32(smem);
    const int tid = threadIdx.x, lane = tid & 31, wid = tid >> 5;
    const int warpM = wid & 1, warpN = wid >> 1;
    const int z = blockIdx.z, b = z/12, h = z%12;
    const int m0 = blockIdx.y*128, n0 = blockIdx.x*128;
    const size_t qbase = (size_t)b*NP*2304 + h*64;

    float d[16][4];
#pragma unroll
    for (int i = 0; i < 16; ++i)
#pragma unroll
        for (int j = 0; j < 4; ++j) d[i][j] = 0.f;

    const int lrow = tid >> 1, lq = tid & 1;
    const int sOff = lrow*144 + lq*64;
    const size_t qr = qbase + (size_t)(m0+lrow)*2304 + lq*32;
    const size_t kr = qbase + 768 + (size_t)(n0+lrow)*2304 + lq*32;
#pragma unroll
    for (int j = 0; j < 4; ++j){
        *(uint4*)(smem + sOff + j*16)         = *(const uint4*)(qh + qr + j*8);
        *(uint4*)(smem + 18432 + sOff + j*16) = *(const uint4*)(qh + kr + j*8);
        *(uint4*)(smem + 36864 + sOff + j*16) = *(const uint4*)(ql + kr + j*8);
    }
    __syncthreads();
    mma2_chunk<4,2,144,144>(sb, 0,  18432,    36864,    warpM*64, warpN*32, lane, d);
    mma2_chunk<4,2,144,144>(sb, 64, 18432+64, 36864+64, warpM*64, warpN*32, lane, d);

    const int g = lane >> 2, tig = lane & 3;
    float* ap = attn + (size_t)z*NP*NP;
#pragma unroll
    for (int mi = 0; mi < 4; ++mi)
#pragma unroll
        for (int ni = 0; ni < 4; ++ni){
            const int n = n0 + warpN*32 + ni*8 + tig*2;
            const int m = m0 + warpM*64 + mi*16 + g;
            *(float2*)(ap + (size_t)m*NP + n) =
                make_float2(d[mi*4+ni][0]*0.125f, d[mi*4+ni][1]*0.125f);
            *(float2*)(ap + (size_t)(m+8)*NP + n) =
                make_float2(d[mi*4+ni][2]*0.125f, d[mi*4+ni][3]*0.125f);
        }
}

// ---------------- attention AV: O = P @ V ----------
// stage (20480B): P@0 (128x80), Vh@10240 (64x80), Vl@15360
#define AV_SMEM 40960
__global__ void __launch_bounds__(256) attnv_tc(const fp16* __restrict__ pP,
                                                const fp16* __restrict__ qh,
                                                const fp16* __restrict__ ql,
                                                fp16* __restrict__ oo){
    extern __shared__ char smem[];
    const uint32_t sb = sm32(smem);
    const int tid = threadIdx.x, lane = tid & 31, wid = tid >> 5;
    const int warpM = wid & 3, warpN = wid >> 2;
    const int z = blockIdx.y, b = z/12, h = z%12;
    const int m0 = blockIdx.x*128;
    const fp16* P = pP + (size_t)z*NP*NP;
    const size_t vbase = (size_t)b*NP*2304 + 1536 + h*64;

    float d[8][4];
#pragma unroll
    for (int i = 0; i < 8; ++i)
#pragma unroll
        for (int j = 0; j < 4; ++j) d[i][j] = 0.f;

    const int lrow = tid >> 1, lq = tid & 1;
    const int sOffA = lrow*80 + lq*32;
    const int vk = tid >> 3, vn8 = tid & 7;

    auto loadP = [&](int kt, uint4* rp){
        const size_t src = (size_t)(m0+lrow)*NP + kt + lq*16;
#pragma unroll
        for (int j = 0; j < 2; ++j) rp[j] = *(const uint4*)(P + src + j*8);
    };
    auto loadV = [&](int kt, uint32_t* vh, uint32_t* vl){
        const size_t src = vbase + (size_t)(kt+vk)*2304 + vn8*8;
#pragma unroll
        for (int w = 0; w < 4; ++w){
            vh[w] = *(const uint32_t*)(qh + src + w*2);
            vl[w] = *(const uint32_t*)(ql + src + w*2);
        }
    };
    auto store = [&](char* base, const uint4* rp, const uint32_t* vh, const uint32_t* vl){
#pragma unroll
        for (int j = 0; j < 2; ++j) *(uint4*)(base + sOffA + j*16) = rp[j];
#pragma unroll
        for (int w = 0; w < 4; ++w){
            const int dc = vn8*8 + w*2;
            *(fp16*)(base + 10240 + dc*80 + vk*2)     = __ushort_as_half((unsigned short)(vh[w] & 0xffff));
            *(fp16*)(base + 10240 + (dc+1)*80 + vk*2) = __ushort_as_half((unsigned short)(vh[w] >> 16));
            *(fp16*)(base + 15360 + dc*80 + vk*2)     = __ushort_as_half((unsigned short)(vl[w] & 0xffff));
            *(fp16*)(base + 15360 + (dc+1)*80 + vk*2) = __ushort_as_half((unsigned short)(vl[w] >> 16));
        }
    };

    {
        uint4 rp[2]; uint32_t vh[4], vl[4];
        loadP(0, rp); loadV(0, vh, vl);
        store(smem, rp, vh, vl);
    }
    __syncthreads();

    for (int t = 0; t < 8; ++t){
        uint4 rp[2]; uint32_t vh[4], vl[4];
        const bool pf = (t + 1 < 8);
        if (pf){ loadP((t+1)*32, rp); loadV((t+1)*32, vh, vl); }
        mma2_chunk<2,2,80,80>(sb + (uint32_t)(t&1)*20480u, 0, 10240, 15360,
                              warpM*32, warpN*32, lane, d);
        if (pf) store(smem + ((t+1)&1)*20480, rp, vh, vl);
        __syncthreads();
    }

    const int g = lane >> 2, tig = lane & 3;
#pragma unroll
    for (int mi = 0; mi < 2; ++mi)
#pragma unroll
        for (int ni = 0; ni < 4; ++ni){
            const int dc = warpN*32 + ni*8 + tig*2;
#pragma unroll
            for (int hr = 0; hr < 2; ++hr){
                const int m = m0 + warpM*32 + mi*16 + g + hr*8;
                const size_t oi = (size_t)(b*NP + m)*DD + h*64 + dc;
                *(uint32_t*)(oo + oi) = packh(__float2half_rn(d[mi*4+ni][hr*2+0]),
                                              __float2half_rn(d[mi*4+ni][hr*2+1]));
            }
        }
}

// ---------------- weight transpose + split ----------------
__global__ void transpose_split(const float* __restrict__ in, fp16* __restrict__ oh,
                                fp16* __restrict__ ol, int K, int N){
    __shared__ float tile[32][33];
    const size_t zoff = (size_t)blockIdx.z * K * N;
    const float* inz = in + zoff;
    const int n0 = blockIdx.x*32, k0 = blockIdx.y*32;
    const int lx = threadIdx.x & 31, ly = threadIdx.x >> 5;
#pragma unroll
    for (int rr = 0; rr < 32; rr += 8)
        tile[ly+rr][lx] = inz[(size_t)(k0+ly+rr)*N + n0+lx];
    __syncthreads();
#pragma unroll
    for (int rr = 0; rr < 32; rr += 8){
        float v = tile[lx][ly+rr];
        fp16 h, l; split1(v, h, l);
        const size_t oi = zoff + (size_t)(n0+ly+rr)*K + k0+lx;
        oh[oi] = h; ol[oi] = l;
    }
}

// ---------------- elementwise / embedding ----------------
__global__ void silu_h_k(const float* __restrict__ in, fp16* __restrict__ o, int n){
    int i = blockIdx.x*256 + threadIdx.x;
    if (i < n) o[i] = __float2half_rn(silu_f(in[i]));
}

__global__ void time_embed_k(const float* __restrict__ t, fp16* __restrict__ o){
    int b = blockIdx.x, j = threadIdx.x;  // 384 threads
    float e = t[b] * expf(-(float)j * (9.210340371976184f / 383.f));
    o[b*DD + j]       = __float2half_rn(sinf(e));
    o[b*DD + 384 + j] = __float2half_rn(cosf(e));
}

__global__ void patchify_k(const float* __restrict__ x, const float* __restrict__ cw,
                           const float* __restrict__ cb, float* __restrict__ tok){
    __shared__ float xv[16];
    const int t = blockIdx.x, tid = threadIdx.x;
    const int b = t>>8, n = t&255, gy = n>>4, gx = n&15;
    if (tid < 16){
        int c = tid>>2, p1 = (tid>>1)&1, p2 = tid&1;
        xv[tid] = x[((b*4+c)*32 + gy*2+p1)*32 + gx*2+p2];
    }
    __syncthreads();
    for (int d = tid; d < DD; d += 256){
        const float4* w4 = (const float4*)(cw + d*16);
        float s = cb[d];
#pragma unroll
        for (int q = 0; q < 4; q++){
            float4 w = w4[q];
            s += xv[q*4+0]*w.x + xv[q*4+1]*w.y + xv[q*4+2]*w.z + xv[q*4+3]*w.w;
        }
        int i2 = d & ~1;
        float ang = (float)n * expf(-(float)i2 * (9.210340371976184f / 768.f));
        float pe = (d & 1) ? cosf(ang) : sinf(ang);
        tok[(size_t)t*DD + d] = s + pe;
    }
}

__global__ void ln_mod_k(const float* __restrict__ in, const float* __restrict__ ada,
                         int adaStride, int shOff, int scOff, fp16* __restrict__ out){
    const int t = blockIdx.x, tid = threadIdx.x;
    const float* row = in + (size_t)t*DD;
    float x0 = row[tid], x1 = row[tid+256], x2 = row[tid+512];
    float sum = x0 + x1 + x2;
    float sq  = fmaf(x0,x0, fmaf(x1,x1, x2*x2));
    __shared__ float s1[8], s2[8];
#pragma unroll
    for (int o = 16; o; o >>= 1){
        sum += __shfl_xor_sync(0xffffffffu, sum, o);
        sq  += __shfl_xor_sync(0xffffffffu, sq,  o);
    }
    if ((tid & 31) == 0){ s1[tid>>5] = sum; s2[tid>>5] = sq; }
    __syncthreads();
    float tot = 0.f, totq = 0.f;
#pragma unroll
    for (int w = 0; w < 8; w++){ tot += s1[w]; totq += s2[w]; }
    float m   = tot * (1.f/768.f);
    float var = totq * (1.f/768.f) - m*m;
    float rr  = rsqrtf(var + 1e-6f);
    const int b = t >> 8;
    const float* sh = ada + (size_t)b*adaStride + shOff;
    const float* sc = ada + (size_t)b*adaStride + scOff;
    const size_t o0 = (size_t)t*DD;
    out[o0 + tid]     = __float2half_rn((x0-m)*rr*(1.f+sc[tid])     + sh[tid]);
    out[o0 + tid+256] = __float2half_rn((x1-m)*rr*(1.f+sc[tid+256]) + sh[tid+256]);
    out[o0 + tid+512] = __float2half_rn((x2-m)*rr*(1.f+sc[tid+512]) + sh[tid+512]);
}

__global__ void softmax_k(const float* __restrict__ attn, fp16* __restrict__ pP){
    const int warp = threadIdx.x>>5, lane = threadIdx.x&31;
    const size_t row = (size_t)blockIdx.x*8 + warp;
    const float* p = attn + row*NP;
    float v[8];
#pragma unroll
    for (int j = 0; j < 8; j++) v[j] = p[lane + j*32];
    float mx = v[0];
#pragma unroll
    for (int j = 1; j < 8; j++) mx = fmaxf(mx, v[j]);
#pragma unroll
    for (int o = 16; o; o >>= 1) mx = fmaxf(mx, __shfl_xor_sync(0xffffffffu, mx, o));
    float s = 0.f;
#pragma unroll
    for (int j = 0; j < 8; j++){ v[j] = expf(v[j]-mx); s += v[j]; }
#pragma unroll
    for (int o = 16; o; o >>= 1) s += __shfl_xor_sync(0xffffffffu, s, o);
    const float inv = 1.f/s;
#pragma unroll
    for (int j = 0; j < 8; j++)
        pP[row*NP + lane + j*32] = __float2half_rn(v[j]*inv);
}

// ---------------- final head + unpatchify ----------------
__global__ void final_k(const fp16* __restrict__ hmod, const float* __restrict__ w,
                        const float* __restrict__ bias, float* __restrict__ out){
    __shared__ float row[768];
    __shared__ float red[128];
    const int t = blockIdx.x, tid = threadIdx.x;  // 128 threads
#pragma unroll
    for (int rr = 0; rr < 6; rr++)
        row[tid + rr*128] = __half2float(hmod[(size_t)t*DD + tid + rr*128]);
    __syncthreads();
    const int j = tid & 15, p = tid >> 4;
    float s = 0.f;
#pragma unroll 8
    for (int k = p*96; k < p*96 + 96; ++k) s = fmaf(row[k], w[k*16 + j], s);
    red[tid] = s;
    __syncthreads();
    if (tid < 16){
        float tot = bias[tid];
#pragma unroll
        for (int q = 0; q < 8; q++) tot += red[q*16 + tid];
        const int b = t>>8, n = t&255, gy = n>>4, gx = n&15;
        const int c = tid&3, pq = tid>>2, p1 = pq>>1, p2 = pq&1;
        out[((b*4+c)*32 + gy*2+p1)*32 + gx*2+p2] = tot;
    }
}

// ---------------- host launcher ----------------
extern "C" void kernel_launch(void* const* d_in, const int* in_sizes, int n_in,
                              void* d_out, int out_size){
    (void)in_sizes; (void)n_in; (void)out_size;
    const float* x     = (const float*)d_in[0];
    const float* tt    = (const float*)d_in[1];
    const float* convw = (const float*)d_in[2];
    const float* convb = (const float*)d_in[3];
    const float* tw1   = (const float*)d_in[4];
    const float* tb1   = (const float*)d_in[5];
    const float* tw2   = (const float*)d_in[6];
    const float* tb2   = (const float*)d_in[7];
    const float* cls   = (const float*)d_in[8];
    const float* qkvw  = (const float*)d_in[9];
    const float* qkvb  = (const float*)d_in[10];
    const float* ow    = (const float*)d_in[11];
    const float* ob    = (const float*)d_in[12];
    const float* aw    = (const float*)d_in[13];
    const float* ab    = (const float*)d_in[14];
    const float* m1w   = (const float*)d_in[15];
    const float* m1b   = (const float*)d_in[16];
    const float* m2w   = (const float*)d_in[17];
    const float* m2b   = (const float*)d_in[18];
    const float* faw   = (const float*)d_in[19];
    const float* fab   = (const float*)d_in[20];
    const float* flw   = (const float*)d_in[21];
    const float* flb   = (const float*)d_in[22];
    const int*   lab   = (const int*)d_in[23];
    float* out = (float*)d_out;

    float *tok,*attn,*c,*ada,*adaf;
    fp16 *hmod,*qkvh,*qkvl,*pP,*oo,*hmid,*c0,*tmid,*sc;
    fp16 *qkvwh,*qkvwl,*owh,*owl,*m1wh,*m1wl,*m2wh,*m2wl,*awh,*awl;
    fp16 *tw1h,*tw1l,*tw2h,*tw2l,*fawh,*fawl;
    cudaGetSymbolAddress((void**)&tok,  g_tok);
    cudaGetSymbolAddress((void**)&attn, g_attn);
    cudaGetSymbolAddress((void**)&c,    g_c);
    cudaGetSymbolAddress((void**)&ada,  g_ada);
    cudaGetSymbolAddress((void**)&adaf, g_adaf);
    cudaGetSymbolAddress((void**)&hmod, g_hmod);
    cudaGetSymbolAddress((void**)&qkvh, g_qkvh);  cudaGetSymbolAddress((void**)&qkvl, g_qkvl);
    cudaGetSymbolAddress((void**)&pP,   g_pP);
    cudaGetSymbolAddress((void**)&oo,   g_oo);
    cudaGetSymbolAddress((void**)&hmid, g_hmid);
    cudaGetSymbolAddress((void**)&c0,   g_c0);
    cudaGetSymbolAddress((void**)&tmid, g_tmid);
    cudaGetSymbolAddress((void**)&sc,   g_sc);
    cudaGetSymbolAddress((void**)&qkvwh,g_qkvwh); cudaGetSymbolAddress((void**)&qkvwl,g_qkvwl);
    cudaGetSymbolAddress((void**)&owh,  g_owh);   cudaGetSymbolAddress((void**)&owl,  g_owl);
    cudaGetSymbolAddress((void**)&m1wh, g_m1wh);  cudaGetSymbolAddress((void**)&m1wl, g_m1wl);
    cudaGetSymbolAddress((void**)&m2wh, g_m2wh);  cudaGetSymbolAddress((void**)&m2wl, g_m2wl);
    cudaGetSymbolAddress((void**)&awh,  g_awh);   cudaGetSymbolAddress((void**)&awl,  g_awl);
    cudaGetSymbolAddress((void**)&tw1h, g_tw1h);  cudaGetSymbolAddress((void**)&tw1l, g_tw1l);
    cudaGetSymbolAddress((void**)&tw2h, g_tw2h);  cudaGetSymbolAddress((void**)&tw2l, g_tw2l);
    cudaGetSymbolAddress((void**)&fawh, g_fawh);  cudaGetSymbolAddress((void**)&fawl, g_fawl);

    cudaFuncSetAttribute(gemm_fp16<0>, cudaFuncAttributeMaxDynamicSharedMemorySize, GSM);
    cudaFuncSetAttribute(gemm_fp16<1>, cudaFuncAttributeMaxDynamicSharedMemorySize, GSM);
    cudaFuncSetAttribute(gemm_fp16<2>, cudaFuncAttributeMaxDynamicSharedMemorySize, GSM);
    cudaFuncSetAttribute(gemm_fp16<3>, cudaFuncAttributeMaxDynamicSharedMemorySize, GSM);
    cudaFuncSetAttribute(gemm_fp16<4>, cudaFuncAttributeMaxDynamicSharedMemorySize, GSM);
    cudaFuncSetAttribute(gemm_fp16<5>, cudaFuncAttributeMaxDynamicSharedMemorySize, GSM);
    cudaFuncSetAttribute(scores_tc,  cudaFuncAttributeMaxDynamicSharedMemorySize, SC_SMEM);
    cudaFuncSetAttribute(attnv_tc,   cudaFuncAttributeMaxDynamicSharedMemorySize, AV_SMEM);

    // weight transpose + split: [K,N] -> [N,K] hi/lo fp16
    transpose_split<<<dim3(HID/32, DD/32, 1),  256>>>(tw1,  tw1h, tw1l, DD,  HID);
    transpose_split<<<dim3(DD/32,  HID/32, 1), 256>>>(tw2,  tw2h, tw2l, HID, DD);
    transpose_split<<<dim3(2*DD/32, DD/32, 1), 256>>>(faw,  fawh, fawl, DD,  2*DD);
    transpose_split<<<dim3(3*DD/32, DD/32, LL),256>>>(qkvw, qkvwh,qkvwl,DD,  3*DD);
    transpose_split<<<dim3(DD/32,  DD/32, LL), 256>>>(ow,   owh,  owl,  DD,  DD);
    transpose_split<<<dim3(6*DD/32, DD/32, LL),256>>>(aw,   awh,  awl,  DD,  6*DD);
    transpose_split<<<dim3(HID/32, DD/32, LL), 256>>>(m1w,  m1wh, m1wl, DD,  HID);
    transpose_split<<<dim3(DD/32,  HID/32, LL),256>>>(m2w,  m2wh, m2wl, HID, DD);

    patchify_k<<<TT, 256>>>(x, convw, convb, tok);
    time_embed_k<<<BB, 384>>>(tt, c0);

    // conditioning
    gemm_fp16<3><<<dim3(HID/128, 1, 1), 256, GSM>>>(c0, DD, tw1h, tw1l, tb1,
        nullptr, tmid, nullptr, 32, HID, DD, nullptr, 0, nullptr, 0, 0, 0);
    gemm_fp16<4><<<dim3(DD/128, 1, 1), 256, GSM>>>(tmid, HID, tw2h, tw2l, tb2,
        c, nullptr, nullptr, 32, DD, HID, cls, 0, lab, 0, 0, 0);
    silu_h_k<<<(BB*DD + 255)/256, 256>>>(c, sc, BB*DD);
    gemm_fp16<0><<<dim3(6*DD/128, 1, LL), 256, GSM>>>(sc, DD, awh, awl, ab,
        ada, nullptr, nullptr, 32, 6*DD, DD, nullptr, 0, nullptr,
        (long long)6*DD*DD, (long long)6*DD, (long long)BB*6*DD);

    for (int i = 0; i < LL; i++){
        const float* adaL = ada + (size_t)i*BB*6*DD;
        // attention branch
        ln_mod_k<<<TT, 256>>>(tok, adaL, 6*DD, 0, DD, hmod);
        gemm_fp16<5><<<dim3(3*DD/128, TT/128, 1), 256, GSM>>>(hmod, DD,
            qkvwh + (size_t)i*3*DD*DD, qkvwl + (size_t)i*3*DD*DD, qkvb + (size_t)i*3*DD,
            nullptr, qkvh, qkvl, TT, 3*DD, DD, nullptr, 0, nullptr, 0, 0, 0);
        scores_tc<<<dim3(2, 2, BHH), 256, SC_SMEM>>>(qkvh, qkvl, attn);
        softmax_k<<<(BHH*NP)/8, 256>>>(attn, pP);
        attnv_tc<<<dim3(2, BHH), 256, AV_SMEM>>>(pP, qkvh, qkvl, oo);
        gemm_fp16<2><<<dim3(DD/128, TT/128, 1), 256, GSM>>>(oo, DD,
            owh + (size_t)i*DD*DD, owl + (size_t)i*DD*DD, ob + (size_t)i*DD,
            tok, nullptr, nullptr, TT, DD, DD, adaL, 2*DD, nullptr, 0, 0, 0);
        // mlp branch
        ln_mod_k<<<TT, 256>>>(tok, adaL, 6*DD, 3*DD, 4*DD, hmod);
        gemm_fp16<1><<<dim3(HID/128, TT/128, 1), 256, GSM>>>(hmod, DD,
            m1wh + (size_t)i*HID*DD, m1wl + (size_t)i*HID*DD, m1b + (size_t)i*HID,
            nullptr, hmid, nullptr, TT, HID, DD, nullptr, 0, nullptr, 0, 0, 0);
        gemm_fp16<2><<<dim3(DD/128, TT/128, 1), 256, GSM>>>(hmid, HID,
            m2wh + (size_t)i*DD*HID, m2wl + (size_t)i*DD*HID, m2b + (size_t)i*DD,
            tok, nullptr, nullptr, TT, DD, HID, adaL, 5*DD, nullptr, 0, 0, 0);
    }

    gemm_fp16<0><<<dim3(2*DD/128, 1, 1), 256, GSM>>>(sc, DD, fawh, fawl, fab,
        adaf, nullptr, nullptr, 32, 2*DD, DD, nullptr, 0, nullptr, 0, 0, 0);
    ln_mod_k<<<TT, 256>>>(tok, adaf, 2*DD, 0, DD, hmod);
    final_k<<<TT, 128>>>(hmod, flw, flb, out);
}

// round 8
// speedup vs baseline: 5.2241x; 1.5311x over previous
#include <cuda_runtime.h>
#include <cuda_fp16.h>
#include <math.h>
#include <stdint.h>

#define BB   32
#define DD   768
#define LL   12
#define HID  3072
#define NP   256
#define TT   8192
#define BHH  384

typedef __half fp16;

// ---------------- scratch (static device allocations) ----------------
__device__ float g_tok [TT*DD];
__device__ float g_c   [BB*DD];
__device__ float g_ada [LL*BB*6*DD];
__device__ float g_adaf[BB*2*DD];
// fp16 activations
__device__ fp16 g_hmod[TT*DD];
__device__ fp16 g_qkv[(size_t)TT*3*DD];
__device__ fp16 g_pP[(size_t)BHH*NP*NP];
__device__ fp16 g_oo[TT*DD];
__device__ fp16 g_hmid[(size_t)TT*HID];
__device__ fp16 g_c0 [128*DD];      // rows 32..127 stay zero
__device__ fp16 g_tmid[(size_t)128*HID];
__device__ fp16 g_sc [128*DD];
// transposed fp16 weights [N][K]
__device__ fp16 g_qkvwT[(size_t)LL*3*DD*DD];
__device__ fp16 g_owT [(size_t)LL*DD*DD];
__device__ fp16 g_m1wT[(size_t)LL*HID*DD];
__device__ fp16 g_m2wT[(size_t)LL*DD*HID];
__device__ fp16 g_awT [(size_t)LL*6*DD*DD];
__device__ fp16 g_tw1T[(size_t)HID*DD];
__device__ fp16 g_tw2T[(size_t)DD*HID];
__device__ fp16 g_fawT[(size_t)2*DD*DD];

// ---------------- helpers ----------------
__device__ __forceinline__ uint32_t sm32(const void* p){
    uint32_t a;
    asm("{ .reg .u64 t; cvta.to.shared.u64 t, %1; cvt.u32.u64 %0, t; }" : "=r"(a) : "l"(p));
    return a;
}
__device__ __forceinline__ void cp16(uint32_t dst, const void* src){
    asm volatile("cp.async.cg.shared.global [%0], [%1], 16;" :: "r"(dst), "l"(src) : "memory");
}
__device__ __forceinline__ void ldsm4(uint32_t* r, uint32_t addr){
    asm volatile("ldmatrix.sync.aligned.m8n8.x4.shared.b16 {%0,%1,%2,%3}, [%4];"
        : "=r"(r[0]), "=r"(r[1]), "=r"(r[2]), "=r"(r[3]) : "r"(addr));
}
__device__ __forceinline__ void mmaf16(float* d, const uint32_t* a, uint32_t b0, uint32_t b1){
    asm volatile("mma.sync.aligned.m16n8k16.row.col.f32.f16.f16.f32 "
        "{%0,%1,%2,%3}, {%4,%5,%6,%7}, {%8,%9}, {%0,%1,%2,%3};"
        : "+f"(d[0]), "+f"(d[1]), "+f"(d[2]), "+f"(d[3])
        : "r"(a[0]), "r"(a[1]), "r"(a[2]), "r"(a[3]), "r"(b0), "r"(b1));
}
__device__ __forceinline__ uint32_t packh(fp16 a, fp16 b){
    return (uint32_t)__half_as_ushort(a) | ((uint32_t)__half_as_ushort(b) << 16);
}
__device__ __forceinline__ float gelu_f(float x){
    return 0.5f * x * (1.0f + erff(x * 0.7071067811865475f));
}
__device__ __forceinline__ float silu_f(float x){
    return x / (1.f + expf(-x));
}

// ---- fp16 single-term K=32 chunk: A at oA (stride RSA), B at oB (stride RSB)
template<int MI, int NPAIRS, int RSA, int RSB>
__device__ __forceinline__ void mma1_chunk(uint32_t sb, int oA, int oB,
                                           int mrow0, int ncol0, int lane, float (*d)[4]){
    const int r8 = lane & 7, t1 = (lane >> 3) & 1, t2 = (lane >> 4) & 1;
#pragma unroll
    for (int ks = 0; ks < 2; ++ks){
        uint32_t a[MI][4], b[NPAIRS][4];
        const int keA = ks*16 + t2*8;
        const int keB = ks*16 + t1*8;
#pragma unroll
        for (int mi = 0; mi < MI; ++mi)
            ldsm4(a[mi], sb + oA + (mrow0 + mi*16 + r8 + t1*8)*RSA + keA*2);
#pragma unroll
        for (int p = 0; p < NPAIRS; ++p)
            ldsm4(b[p], sb + oB + (ncol0 + p*16 + r8 + t2*8)*RSB + keB*2);
#pragma unroll
        for (int mi = 0; mi < MI; ++mi)
#pragma unroll
            for (int p = 0; p < NPAIRS; ++p){
                mmaf16(d[mi*(NPAIRS*2)+p*2],   a[mi], b[p][0], b[p][1]);
                mmaf16(d[mi*(NPAIRS*2)+p*2+1], a[mi], b[p][2], b[p][3]);
            }
    }
}

// ---------------- main GEMM: out[M,N] = A[M,K] @ W[N,K]^T ----------
// 128x128 CTA, 8 warps of 64x32, 3-stage cp.async, 2 CTAs/SM.
// stage (20480B): A@0 (128x80), W@10240 (128x80)
#define STG 20480
#define GSM (3*STG)
// EPI: 0 fp32 | 1 gelu fp16 | 2 gated residual fp32 | 3 silu fp16 | 4 +cls fp32 | 5 fp16
template<int EPI>
__global__ void __launch_bounds__(256, 2) gemm_fp16(
    const fp16* __restrict__ A, int lda,
    const fp16* __restrict__ W,
    const float* __restrict__ bias,
    float* __restrict__ outF, fp16* __restrict__ outH,
    int Mvalid, int N, int K,
    const float* __restrict__ aux, int auxOff, const int* __restrict__ lab,
    long long wz, long long bz, long long oz)
{
    extern __shared__ char smem[];
    const uint32_t sb = sm32(smem);
    const int tid = threadIdx.x, lane = tid & 31, wid = tid >> 5;
    const int warpM = wid & 1, warpN = wid >> 1;
    const int m0 = blockIdx.y*128, n0 = blockIdx.x*128, z = blockIdx.z;
    const fp16* WZ = W + (size_t)z*wz;
    const float* BzP = bias + (size_t)z*bz;

    float d[16][4];
#pragma unroll
    for (int i = 0; i < 16; ++i)
#pragma unroll
        for (int j = 0; j < 4; ++j) d[i][j] = 0.f;

    auto issue = [&](int s, int t){
        const int kt = t << 5;
        const uint32_t base = sb + s*STG;
#pragma unroll
        for (int it = 0; it < 2; ++it){
            const int idx = tid + it*256;        // 0..511
            const int row = idx >> 2, q = idx & 3;
            const uint32_t dq = row*80 + q*16;
            cp16(base + dq,         (const char*)(A  + (size_t)(m0+row)*lda + kt) + q*16);
            cp16(base + 10240 + dq, (const char*)(WZ + (size_t)(n0+row)*K   + kt) + q*16);
        }
        asm volatile("cp.async.commit_group;" ::: "memory");
    };

    const int nk = K >> 5;
    issue(0, 0); issue(1, 1);
    int stage = 0;
    for (int t = 0; t < nk; ++t){
        asm volatile("cp.async.wait_group 1;" ::: "memory");
        __syncthreads();
        if (t + 2 < nk) issue((stage + 2) % 3, t + 2);
        else asm volatile("cp.async.commit_group;" ::: "memory");
        mma1_chunk<4,2,80,80>(sb + stage*STG, 0, 10240,
                              warpM*64, warpN*32, lane, d);
        stage = (stage + 1) % 3;
    }

    const int g = lane >> 2, tig = lane & 3;
#pragma unroll
    for (int mi = 0; mi < 4; ++mi){
#pragma unroll
        for (int ni = 0; ni < 4; ++ni){
            const int n = n0 + warpN*32 + ni*8 + tig*2;
            const float2 bv = *(const float2*)(BzP + n);
#pragma unroll
            for (int hr = 0; hr < 2; ++hr){
                const int m = m0 + warpM*64 + mi*16 + g + hr*8;
                if (m < Mvalid){
                    float x0 = d[mi*4+ni][hr*2+0] + bv.x;
                    float x1 = d[mi*4+ni][hr*2+1] + bv.y;
                    const size_t oi = (size_t)m*N + n;
                    if (EPI == 0){
                        *(float2*)(outF + (size_t)z*oz + oi) = make_float2(x0, x1);
                    } else if (EPI == 2){
                        const float2 gv = *(const float2*)(aux + (size_t)(m>>8)*(6*DD) + auxOff + n);
                        float2 ov = *(float2*)(outF + oi);
                        *(float2*)(outF + oi) = make_float2(ov.x + gv.x*x0, ov.y + gv.y*x1);
                    } else if (EPI == 4){
                        const float2 cv = *(const float2*)(aux + (size_t)lab[m]*DD + n);
                        *(float2*)(outF + oi) = make_float2(x0 + cv.x, x1 + cv.y);
                    } else {
                        if (EPI == 1){ x0 = gelu_f(x0); x1 = gelu_f(x1); }
                        else if (EPI == 3){ x0 = silu_f(x0); x1 = silu_f(x1); }
                        *(uint32_t*)(outH + oi) = packh(__float2half_rn(x0), __float2half_rn(x1));
                    }
                }
            }
        }
    }
}

// ---------------- fused scores+softmax: P = softmax(Q K^T / 8) ----------
// CTA: 128 rows x all 256 cols. smem: Q@0 (128x144), K@18432 (256x144),
// smax@55296 (4x128 f32), ssum@57344 (4x128 f32). total 59392.
#define SS_SMEM 59392
__global__ void __launch_bounds__(256) scores_softmax(const fp16* __restrict__ qkv,
                                                      fp16* __restrict__ pP){
    extern __shared__ char smem[];
    const uint32_t sb = sm32(smem);
    const int tid = threadIdx.x, lane = tid & 31, wid = tid >> 5;
    const int warpM = wid & 1, warpN = wid >> 1;      // warp tile 64 x 64
    const int z = blockIdx.y, b = z/12, h = z%12;
    const int m0 = blockIdx.x*128;
    const size_t qbase = (size_t)b*NP*2304 + h*64;

    // load Q (128 rows) and K (256 rows)
    {
        const int lrow = tid >> 1, lq = tid & 1;
        const size_t qr = qbase + (size_t)(m0+lrow)*2304 + lq*32;
#pragma unroll
        for (int j = 0; j < 4; ++j)
            *(uint4*)(smem + lrow*144 + lq*64 + j*16) = *(const uint4*)(qkv + qr + j*8);
        const size_t kr = qbase + 768 + (size_t)tid*2304;
#pragma unroll
        for (int j = 0; j < 8; ++j)
            *(uint4*)(smem + 18432 + tid*144 + j*16) = *(const uint4*)(qkv + kr + j*8);
    }
    __syncthreads();

    float d[32][4];
#pragma unroll
    for (int i = 0; i < 32; ++i)
#pragma unroll
        for (int j = 0; j < 4; ++j) d[i][j] = 0.f;

    mma1_chunk<4,4,144,144>(sb, 0,  18432,    warpM*64, warpN*64, lane, d);
    mma1_chunk<4,4,144,144>(sb, 64, 18432+64, warpM*64, warpN*64, lane, d);

    const int g = lane >> 2, tig = lane & 3;
    float* smax = (float*)(smem + 55296);
    float* ssum = (float*)(smem + 57344);

#pragma unroll
    for (int i = 0; i < 32; ++i)
#pragma unroll
        for (int j = 0; j < 4; ++j) d[i][j] *= 0.125f;

    // row max: local -> quad shuffle -> cross-warpN via smem
    float rmx[4][2];
#pragma unroll
    for (int mi = 0; mi < 4; ++mi)
#pragma unroll
        for (int hr = 0; hr < 2; ++hr){
            float m = -1e30f;
#pragma unroll
            for (int ni = 0; ni < 8; ++ni)
                m = fmaxf(m, fmaxf(d[mi*8+ni][hr*2], d[mi*8+ni][hr*2+1]));
            m = fmaxf(m, __shfl_xor_sync(0xffffffffu, m, 1));
            m = fmaxf(m, __shfl_xor_sync(0xffffffffu, m, 2));
            rmx[mi][hr] = m;
            if (tig == 0) smax[warpN*128 + warpM*64 + mi*16 + g + hr*8] = m;
        }
    __syncthreads();
#pragma unroll
    for (int mi = 0; mi < 4; ++mi)
#pragma unroll
        for (int hr = 0; hr < 2; ++hr){
            const int r = warpM*64 + mi*16 + g + hr*8;
            rmx[mi][hr] = fmaxf(fmaxf(smax[r], smax[128+r]),
                                fmaxf(smax[256+r], smax[384+r]));
        }
    // exp + row sum
    float rsm[4][2];
#pragma unroll
    for (int mi = 0; mi < 4; ++mi)
#pragma unroll
        for (int hr = 0; hr < 2; ++hr){
            float s = 0.f;
            const float m = rmx[mi][hr];
#pragma unroll
            for (int ni = 0; ni < 8; ++ni){
                float e0 = expf(d[mi*8+ni][hr*2]   - m);
                float e1 = expf(d[mi*8+ni][hr*2+1] - m);
                d[mi*8+ni][hr*2] = e0; d[mi*8+ni][hr*2+1] = e1;
                s += e0 + e1;
            }
            s += __shfl_xor_sync(0xffffffffu, s, 1);
            s += __shfl_xor_sync(0xffffffffu, s, 2);
            rsm[mi][hr] = s;
            if (tig == 0) ssum[warpN*128 + warpM*64 + mi*16 + g + hr*8] = s;
        }
    __syncthreads();
    fp16* pp = pP + (size_t)z*NP*NP;
#pragma unroll
    for (int mi = 0; mi < 4; ++mi)
#pragma unroll
        for (int hr = 0; hr < 2; ++hr){
            const int r = warpM*64 + mi*16 + g + hr*8;
            const float inv = 1.f / (ssum[r] + ssum[128+r] + ssum[256+r] + ssum[384+r]);
            const int m = m0 + r;
#pragma unroll
            for (int ni = 0; ni < 8; ++ni){
                const int n = warpN*64 + ni*8 + tig*2;
                *(uint32_t*)(pp + (size_t)m*NP + n) =
                    packh(__float2half_rn(d[mi*8+ni][hr*2]*inv),
                          __float2half_rn(d[mi*8+ni][hr*2+1]*inv));
            }
        }
}

// ---------------- attention AV: O = P @ V ----------
// stage (15360B): P@0 (128x80), V@10240 (64x80)
#define AV_SMEM 30720
__global__ void __launch_bounds__(256) attnv_tc(const fp16* __restrict__ pP,
                                                const fp16* __restrict__ qkv,
                                                fp16* __restrict__ oo){
    extern __shared__ char smem[];
    const uint32_t sb = sm32(smem);
    const int tid = threadIdx.x, lane = tid & 31, wid = tid >> 5;
    const int warpM = wid & 3, warpN = wid >> 2;
    const int z = blockIdx.y, b = z/12, h = z%12;
    const int m0 = blockIdx.x*128;
    const fp16* P = pP + (size_t)z*NP*NP;
    const size_t vbase = (size_t)b*NP*2304 + 1536 + h*64;

    float d[8][4];
#pragma unroll
    for (int i = 0; i < 8; ++i)
#pragma unroll
        for (int j = 0; j < 4; ++j) d[i][j] = 0.f;

    const int lrow = tid >> 1, lq = tid & 1;
    const int sOffA = lrow*80 + lq*32;
    const int vk = tid >> 3, vn8 = tid & 7;

    auto loadP = [&](int kt, uint4* rp){
        const size_t src = (size_t)(m0+lrow)*NP + kt + lq*16;
#pragma unroll
        for (int j = 0; j < 2; ++j) rp[j] = *(const uint4*)(P + src + j*8);
    };
    auto loadV = [&](int kt, uint32_t* vh){
        const size_t src = vbase + (size_t)(kt+vk)*2304 + vn8*8;
#pragma unroll
        for (int w = 0; w < 4; ++w) vh[w] = *(const uint32_t*)(qkv + src + w*2);
    };
    auto store = [&](char* base, const uint4* rp, const uint32_t* vh){
#pragma unroll
        for (int j = 0; j < 2; ++j) *(uint4*)(base + sOffA + j*16) = rp[j];
#pragma unroll
        for (int w = 0; w < 4; ++w){
            const int dc = vn8*8 + w*2;
            *(fp16*)(base + 10240 + dc*80 + vk*2)     = __ushort_as_half((unsigned short)(vh[w] & 0xffff));
            *(fp16*)(base + 10240 + (dc+1)*80 + vk*2) = __ushort_as_half((unsigned short)(vh[w] >> 16));
        }
    };

    {
        uint4 rp[2]; uint32_t vh[4];
        loadP(0, rp); loadV(0, vh);
        store(smem, rp, vh);
    }
    __syncthreads();

    for (int t = 0; t < 8; ++t){
        uint4 rp[2]; uint32_t vh[4];
        const bool pf = (t + 1 < 8);
        if (pf){ loadP((t+1)*32, rp); loadV((t+1)*32, vh); }
        mma1_chunk<2,2,80,80>(sb + (uint32_t)(t&1)*15360u, 0, 10240,
                              warpM*32, warpN*32, lane, d);
        if (pf) store(smem + ((t+1)&1)*15360, rp, vh);
        __syncthreads();
    }

    const int g = lane >> 2, tig = lane & 3;
#pragma unroll
    for (int mi = 0; mi < 2; ++mi)
#pragma unroll
        for (int ni = 0; ni < 4; ++ni){
            const int dc = warpN*32 + ni*8 + tig*2;
#pragma unroll
            for (int hr = 0; hr < 2; ++hr){
                const int m = m0 + warpM*32 + mi*16 + g + hr*8;
                const size_t oi = (size_t)(b*NP + m)*DD + h*64 + dc;
                *(uint32_t*)(oo + oi) = packh(__float2half_rn(d[mi*4+ni][hr*2+0]),
                                              __float2half_rn(d[mi*4+ni][hr*2+1]));
            }
        }
}

// ---------------- weight transpose -> fp16 ----------------
__global__ void transpose_h(const float* __restrict__ in, fp16* __restrict__ oh,
                            int K, int N){
    __shared__ float tile[32][33];
    const size_t zoff = (size_t)blockIdx.z * K * N;
    const float* inz = in + zoff;
    const int n0 = blockIdx.x*32, k0 = blockIdx.y*32;
    const int lx = threadIdx.x & 31, ly = threadIdx.x >> 5;
#pragma unroll
    for (int rr = 0; rr < 32; rr += 8)
        tile[ly+rr][lx] = inz[(size_t)(k0+ly+rr)*N + n0+lx];
    __syncthreads();
#pragma unroll
    for (int rr = 0; rr < 32; rr += 8)
        oh[zoff + (size_t)(n0+ly+rr)*K + k0+lx] = __float2half_rn(tile[lx][ly+rr]);
}

// ---------------- elementwise / embedding ----------------
__global__ void silu_h_k(const float* __restrict__ in, fp16* __restrict__ o, int n){
    int i = blockIdx.x*256 + threadIdx.x;
    if (i < n) o[i] = __float2half_rn(silu_f(in[i]));
}

__global__ void time_embed_k(const float* __restrict__ t, fp16* __restrict__ o){
    int b = blockIdx.x, j = threadIdx.x;  // 384 threads
    float e = t[b] * expf(-(float)j * (9.210340371976184f / 383.f));
    o[b*DD + j]       = __float2half_rn(sinf(e));
    o[b*DD + 384 + j] = __float2half_rn(cosf(e));
}

__global__ void patchify_k(const float* __restrict__ x, const float* __restrict__ cw,
                           const float* __restrict__ cb, float* __restrict__ tok){
    __shared__ float xv[16];
    const int t = blockIdx.x, tid = threadIdx.x;
    const int b = t>>8, n = t&255, gy = n>>4, gx = n&15;
    if (tid < 16){
        int c = tid>>2, p1 = (tid>>1)&1, p2 = tid&1;
        xv[tid] = x[((b*4+c)*32 + gy*2+p1)*32 + gx*2+p2];
    }
    __syncthreads();
    for (int d = tid; d < DD; d += 256){
        const float4* w4 = (const float4*)(cw + d*16);
        float s = cb[d];
#pragma unroll
        for (int q = 0; q < 4; q++){
            float4 w = w4[q];
            s += xv[q*4+0]*w.x + xv[q*4+1]*w.y + xv[q*4+2]*w.z + xv[q*4+3]*w.w;
        }
        int i2 = d & ~1;
        float ang = (float)n * expf(-(float)i2 * (9.210340371976184f / 768.f));
        float pe = (d & 1) ? cosf(ang) : sinf(ang);
        tok[(size_t)t*DD + d] = s + pe;
    }
}

__global__ void ln_mod_k(const float* __restrict__ in, const float* __restrict__ ada,
                         int adaStride, int shOff, int scOff, fp16* __restrict__ out){
    const int t = blockIdx.x, tid = threadIdx.x;
    const float* row = in + (size_t)t*DD;
    float x0 = row[tid], x1 = row[tid+256], x2 = row[tid+512];
    float sum = x0 + x1 + x2;
    float sq  = fmaf(x0,x0, fmaf(x1,x1, x2*x2));
    __shared__ float s1[8], s2[8];
#pragma unroll
    for (int o = 16; o; o >>= 1){
        sum += __shfl_xor_sync(0xffffffffu, sum, o);
        sq  += __shfl_xor_sync(0xffffffffu, sq,  o);
    }
    if ((tid & 31) == 0){ s1[tid>>5] = sum; s2[tid>>5] = sq; }
    __syncthreads();
    float tot = 0.f, totq = 0.f;
#pragma unroll
    for (int w = 0; w < 8; w++){ tot += s1[w]; totq += s2[w]; }
    float m   = tot * (1.f/768.f);
    float var = totq * (1.f/768.f) - m*m;
    float rr  = rsqrtf(var + 1e-6f);
    const int b = t >> 8;
    const float* sh = ada + (size_t)b*adaStride + shOff;
    const float* sc = ada + (size_t)b*adaStride + scOff;
    const size_t o0 = (size_t)t*DD;
    out[o0 + tid]     = __float2half_rn((x0-m)*rr*(1.f+sc[tid])     + sh[tid]);
    out[o0 + tid+256] = __float2half_rn((x1-m)*rr*(1.f+sc[tid+256]) + sh[tid+256]);
    out[o0 + tid+512] = __float2half_rn((x2-m)*rr*(1.f+sc[tid+512]) + sh[tid+512]);
}

// ---------------- final head + unpatchify ----------------
__global__ void final_k(const fp16* __restrict__ hmod, const float* __restrict__ w,
                        const float* __restrict__ bias, float* __restrict__ out){
    __shared__ float row[768];
    __shared__ float red[128];
    const int t = blockIdx.x, tid = threadIdx.x;  // 128 threads
#pragma unroll
    for (int rr = 0; rr < 6; rr++)
        row[tid + rr*128] = __half2float(hmod[(size_t)t*DD + tid + rr*128]);
    __syncthreads();
    const int j = tid & 15, p = tid >> 4;
    float s = 0.f;
#pragma unroll 8
    for (int k = p*96; k < p*96 + 96; ++k) s = fmaf(row[k], w[k*16 + j], s);
    red[tid] = s;
    __syncthreads();
    if (tid < 16){
        float tot = bias[tid];
#pragma unroll
        for (int q = 0; q < 8; q++) tot += red[q*16 + tid];
        const int b = t>>8, n = t&255, gy = n>>4, gx = n&15;
        const int c = tid&3, pq = tid>>2, p1 = pq>>1, p2 = pq&1;
        out[((b*4+c)*32 + gy*2+p1)*32 + gx*2+p2] = tot;
    }
}

// ---------------- host launcher ----------------
extern "C" void kernel_launch(void* const* d_in, const int* in_sizes, int n_in,
                              void* d_out, int out_size){
    (void)in_sizes; (void)n_in; (void)out_size;
    const float* x     = (const float*)d_in[0];
    const float* tt    = (const float*)d_in[1];
    const float* convw = (const float*)d_in[2];
    const float* convb = (const float*)d_in[3];
    const float* tw1   = (const float*)d_in[4];
    const float* tb1   = (const float*)d_in[5];
    const float* tw2   = (const float*)d_in[6];
    const float* tb2   = (const float*)d_in[7];
    const float* cls   = (const float*)d_in[8];
    const float* qkvw  = (const float*)d_in[9];
    const float* qkvb  = (const float*)d_in[10];
    const float* ow    = (const float*)d_in[11];
    const float* ob    = (const float*)d_in[12];
    const float* aw    = (const float*)d_in[13];
    const float* ab    = (const float*)d_in[14];
    const float* m1w   = (const float*)d_in[15];
    const float* m1b   = (const float*)d_in[16];
    const float* m2w   = (const float*)d_in[17];
    const float* m2b   = (const float*)d_in[18];
    const float* faw   = (const float*)d_in[19];
    const float* fab   = (const float*)d_in[20];
    const float* flw   = (const float*)d_in[21];
    const float* flb   = (const float*)d_in[22];
    const int*   lab   = (const int*)d_in[23];
    float* out = (float*)d_out;

    float *tok,*c,*ada,*adaf;
    fp16 *hmod,*qkv,*pP,*oo,*hmid,*c0,*tmid,*sc;
    fp16 *qkvwT,*owT,*m1wT,*m2wT,*awT,*tw1T,*tw2T,*fawT;
    cudaGetSymbolAddress((void**)&tok,  g_tok);
    cudaGetSymbolAddress((void**)&c,    g_c);
    cudaGetSymbolAddress((void**)&ada,  g_ada);
    cudaGetSymbolAddress((void**)&adaf, g_adaf);
    cudaGetSymbolAddress((void**)&hmod, g_hmod);
    cudaGetSymbolAddress((void**)&qkv,  g_qkv);
    cudaGetSymbolAddress((void**)&pP,   g_pP);
    cudaGetSymbolAddress((void**)&oo,   g_oo);
    cudaGetSymbolAddress((void**)&hmid, g_hmid);
    cudaGetSymbolAddress((void**)&c0,   g_c0);
    cudaGetSymbolAddress((void**)&tmid, g_tmid);
    cudaGetSymbolAddress((void**)&sc,   g_sc);
    cudaGetSymbolAddress((void**)&qkvwT,g_qkvwT);
    cudaGetSymbolAddress((void**)&owT,  g_owT);
    cudaGetSymbolAddress((void**)&m1wT, g_m1wT);
    cudaGetSymbolAddress((void**)&m2wT, g_m2wT);
    cudaGetSymbolAddress((void**)&awT,  g_awT);
    cudaGetSymbolAddress((void**)&tw1T, g_tw1T);
    cudaGetSymbolAddress((void**)&tw2T, g_tw2T);
    cudaGetSymbolAddress((void**)&fawT, g_fawT);

    cudaFuncSetAttribute(gemm_fp16<0>, cudaFuncAttributeMaxDynamicSharedMemorySize, GSM);
    cudaFuncSetAttribute(gemm_fp16<1>, cudaFuncAttributeMaxDynamicSharedMemorySize, GSM);
    cudaFuncSetAttribute(gemm_fp16<2>, cudaFuncAttributeMaxDynamicSharedMemorySize, GSM);
    cudaFuncSetAttribute(gemm_fp16<3>, cudaFuncAttributeMaxDynamicSharedMemorySize, GSM);
    cudaFuncSetAttribute(gemm_fp16<4>, cudaFuncAttributeMaxDynamicSharedMemorySize, GSM);
    cudaFuncSetAttribute(gemm_fp16<5>, cudaFuncAttributeMaxDynamicSharedMemorySize, GSM);
    cudaFuncSetAttribute(scores_softmax, cudaFuncAttributeMaxDynamicSharedMemorySize, SS_SMEM);
    cudaFuncSetAttribute(attnv_tc,   cudaFuncAttributeMaxDynamicSharedMemorySize, AV_SMEM);

    // weight transpose: [K,N] -> [N,K] fp16
    transpose_h<<<dim3(HID/32, DD/32, 1),  256>>>(tw1,  tw1T, DD,  HID);
    transpose_h<<<dim3(DD/32,  HID/32, 1), 256>>>(tw2,  tw2T, HID, DD);
    transpose_h<<<dim3(2*DD/32, DD/32, 1), 256>>>(faw,  fawT, DD,  2*DD);
    transpose_h<<<dim3(3*DD/32, DD/32, LL),256>>>(qkvw, qkvwT,DD,  3*DD);
    transpose_h<<<dim3(DD/32,  DD/32, LL), 256>>>(ow,   owT,  DD,  DD);
    transpose_h<<<dim3(6*DD/32, DD/32, LL),256>>>(aw,   awT,  DD,  6*DD);
    transpose_h<<<dim3(HID/32, DD/32, LL), 256>>>(m1w,  m1wT, DD,  HID);
    transpose_h<<<dim3(DD/32,  HID/32, LL),256>>>(m2w,  m2wT, HID, DD);

    patchify_k<<<TT, 256>>>(x, convw, convb, tok);
    time_embed_k<<<BB, 384>>>(tt, c0);

    // conditioning
    gemm_fp16<3><<<dim3(HID/128, 1, 1), 256, GSM>>>(c0, DD, tw1T, tb1,
        nullptr, tmid, 32, HID, DD, nullptr, 0, nullptr, 0, 0, 0);
    gemm_fp16<4><<<dim3(DD/128, 1, 1), 256, GSM>>>(tmid, HID, tw2T, tb2,
        c, nullptr, 32, DD, HID, cls, 0, lab, 0, 0, 0);
    silu_h_k<<<(BB*DD + 255)/256, 256>>>(c, sc, BB*DD);
    gemm_fp16<0><<<dim3(6*DD/128, 1, LL), 256, GSM>>>(sc, DD, awT, ab,
        ada, nullptr, 32, 6*DD, DD, nullptr, 0, nullptr,
        (long long)6*DD*DD, (long long)6*DD, (long long)BB*6*DD);

    for (int i = 0; i < LL; i++){
        const float* adaL = ada + (size_t)i*BB*6*DD;
        // attention branch
        ln_mod_k<<<TT, 256>>>(tok, adaL, 6*DD, 0, DD, hmod);
        gemm_fp16<5><<<dim3(3*DD/128, TT/128, 1), 256, GSM>>>(hmod, DD,
            qkvwT + (size_t)i*3*DD*DD, qkvb + (size_t)i*3*DD,
            nullptr, qkv, TT, 3*DD, DD, nullptr, 0, nullptr, 0, 0, 0);
        scores_softmax<<<dim3(2, BHH), 256, SS_SMEM>>>(qkv, pP);
        attnv_tc<<<dim3(2, BHH), 256, AV_SMEM>>>(pP, qkv, oo);
        gemm_fp16<2><<<dim3(DD/128, TT/128, 1), 256, GSM>>>(oo, DD,
            owT + (size_t)i*DD*DD, ob + (size_t)i*DD,
            tok, nullptr, TT, DD, DD, adaL, 2*DD, nullptr, 0, 0, 0);
        // mlp branch
        ln_mod_k<<<TT, 256>>>(tok, adaL, 6*DD, 3*DD, 4*DD, hmod);
        gemm_fp16<1><<<dim3(HID/128, TT/128, 1), 256, GSM>>>(hmod, DD,
            m1wT + (size_t)i*HID*DD, m1b + (size_t)i*HID,
            nullptr, hmid, TT, HID, DD, nullptr, 0, nullptr, 0, 0, 0);
        gemm_fp16<2><<<dim3(DD/128, TT/128, 1), 256, GSM>>>(hmid, HID,
            m2wT + (size_t)i*DD*HID, m2b + (size_t)i*DD,
            tok, nullptr, TT, DD, HID, adaL, 5*DD, nullptr, 0, 0, 0);
    }

    gemm_fp16<0><<<dim3(2*DD/128, 1, 1), 256, GSM>>>(sc, DD, fawT, fab,
        adaf, nullptr, 32, 2*DD, DD, nullptr, 0, nullptr, 0, 0, 0);
    ln_mod_k<<<TT, 256>>>(tok, adaf, 2*DD, 0, DD, hmod);
    final_k<<<TT, 128>>>(hmod, flw, flb, out);
}